// round 9
// baseline (speedup 1.0000x reference)
#include <cuda_runtime.h>
#include <cuda_fp16.h>
#include <cstdint>
#include <cstddef>

#define HW   4096
#define NB   32
#define CIN  256
#define CMC  64
#define MTOT 384
#define KCAT 192

// ---------------- scratch (static device globals; no allocation) ----------------
__device__ float  d_msum[NB * 32 * 256];                  // per-(n,pblk) channel sums
__device__ float  d_mean[NB * CIN];
__device__ float  d_ker[NB * CMC * 43];
__device__ float  d_Wcat[MTOT * KCAT];                    // tf32-rounded
__device__ float  d_cbias[MTOT];
__device__ __half d_f[(size_t)NB * CMC * HW];             // 16.8 MB (fp16)
__device__ __half d_ocat[(size_t)NB * KCAT * HW];         // 50.3 MB (fp16)

// ---------------- helpers ----------------
__device__ __forceinline__ float f2tf32(float f) {
    uint32_t r;
    asm("cvt.rna.tf32.f32 %0, %1;" : "=r"(r) : "f"(f));
    return __uint_as_float(r);
}
__device__ __forceinline__ void mma_tf32(float c[4], const uint32_t a[4],
                                         const uint32_t b[2]) {
    asm volatile(
        "mma.sync.aligned.m16n8k8.row.col.f32.tf32.tf32.f32 "
        "{%0,%1,%2,%3}, {%4,%5,%6,%7}, {%8,%9}, {%0,%1,%2,%3};"
        : "+f"(c[0]), "+f"(c[1]), "+f"(c[2]), "+f"(c[3])
        : "r"(a[0]), "r"(a[1]), "r"(a[2]), "r"(a[3]), "r"(b[0]), "r"(b[1]));
}
__device__ __forceinline__ void cp16(void* sptr, const void* g) {
    unsigned sa = (unsigned)__cvta_generic_to_shared(sptr);
    asm volatile("cp.async.cg.shared.global [%0], [%1], 16;" :: "r"(sa), "l"(g));
}
__device__ __forceinline__ void cp_commit() {
    asm volatile("cp.async.commit_group;" ::: "memory");
}
__device__ __forceinline__ float red_g(float v) {
    v += __shfl_xor_sync(0xffffffffu, v, 4);
    v += __shfl_xor_sync(0xffffffffu, v, 8);
    v += __shfl_xor_sync(0xffffffffu, v, 16);
    return v;
}

// ---------------- mean reduce: d_mean[n][c] = sum_pblk d_msum / 4096 ----------------
__global__ void __launch_bounds__(256) mean_reduce_kernel() {
    const int idx = blockIdx.x * 256 + threadIdx.x;  // (n, c)
    float s = 0.f;
#pragma unroll 8
    for (int p = 0; p < 32; p++) s += d_msum[((idx >> 8) * 32 + p) * 256 + (idx & 255)];
    d_mean[idx] = s * (1.f / 4096.f);
}

// ---------------- K2a: g + dynamic kernels ----------------
__global__ void __launch_bounds__(256) gker_kernel(
    const float* __restrict__ conv_w, const float* __restrict__ conv_b,
    const float* __restrict__ ckw, const float* __restrict__ ckb,
    const float* __restrict__ ck2w, const float* __restrict__ ck2b,
    const float* __restrict__ ckd4w, const float* __restrict__ ckd4b,
    const float* __restrict__ kw, const float* __restrict__ kb,
    const float* __restrict__ k2w, const float* __restrict__ k2b,
    const float* __restrict__ kd4w, const float* __restrict__ kd4b) {
    const int t = blockIdx.x * 256 + threadIdx.x;
    const int n = t >> 6, c = t & 63;
    const float* mrow = &d_mean[n * CIN];
    const float* wrow = &conv_w[c * CIN];
    float s = conv_b[c];
#pragma unroll 8
    for (int k = 0; k < CIN; k++) s = fmaf(mrow[k], wrow[k], s);
    const float g = fmaxf(s, 0.f);
    float* kp = &d_ker[(size_t)t * 43];
    float a = *ckw, b = *ckb;
#pragma unroll
    for (int i = 0; i < 25; i++) kp[i] = fmaf(a, fmaf(g, kw[i], kb[i]), b);
    a = *ck2w; b = *ck2b;
#pragma unroll
    for (int i = 0; i < 9; i++) kp[25 + i] = fmaf(a, fmaf(g, k2w[i], k2b[i]), b);
    a = *ckd4w; b = *ckd4b;
#pragma unroll
    for (int i = 0; i < 9; i++) kp[34 + i] = fmaf(a, fmaf(g, kd4w[i], kd4b[i]), b);
}

// ---------------- K2b: collapsed weights Wcat (tf32-rounded) and cbias ----------------
__global__ void __launch_bounds__(256) wcat_kernel(
    const float* __restrict__ fc_w, const float* __restrict__ fc_b,
    const float* __restrict__ fuse_w, const float* __restrict__ fuse_b) {
    const int m = blockIdx.x * 256 + threadIdx.x;
    if (m < MTOT * KCAT) {
        const int o = m / KCAT, cs = m % KCAT;
        const int b = cs >> 6, c = cs & 63;
        const float* fcr = &fc_w[o * 384 + b * 128];
        float s = 0.f;
#pragma unroll 4
        for (int j = 0; j < 128; j++) s = fmaf(fcr[j], fuse_w[j * 64 + c], s);
        d_Wcat[m] = f2tf32(s);
    } else {
        const int o = m - MTOT * KCAT;
        if (o < MTOT) {
            float s = fc_b[o];
            for (int j = 0; j < 384; j++)
                s = fmaf(fc_w[o * 384 + j], fuse_b[j & 127], s);
            d_cbias[o] = s;
        }
    }
}

// ---------------- K3: f = relu(conv_w @ x + b), tf32 mma, fused channel-mean ----------------
// block 64o x 128px, 8 warps (2m x 4n), 3-stage cp.async, fp16 output.
__global__ void __launch_bounds__(256) k3_kernel(
    const float* __restrict__ A, const float* __restrict__ B,
    const float* __restrict__ bias) {
    constexpr int SA = 64 * 20, SB = 16 * 136, SS = SA + SB;  // floats
    constexpr int NKT = CIN / 16;
    extern __shared__ float smem[];
    float* s_msum = smem + 3 * SS;

    const int p0 = blockIdx.y * 128;
    const int n = blockIdx.z;
    const float* Bn = B + (size_t)n * CIN * HW;
    __half* Cn = d_f + (size_t)n * CMC * HW;

    const int tid = threadIdx.x;
    const int wid = tid >> 5, lane = tid & 31;
    const int wm = wid >> 2, wq = wid & 3;
    const int g = lane >> 2, tg = lane & 3;

    s_msum[tid] = 0.f;

    auto issue = [&](int s, int k0) {
        float* As_ = smem + s * SS;
        float* Bs_ = As_ + SA;
        {
            const int row = tid >> 2, kq = (tid & 3) << 2;
            cp16(&As_[row * 20 + kq], &A[(size_t)row * CIN + k0 + kq]);
        }
#pragma unroll
        for (int v = tid; v < 512; v += 256) {
            const int row = v >> 5, c4 = (v & 31) << 2;
            cp16(&Bs_[row * 136 + c4], &Bn[(size_t)(k0 + row) * HW + p0 + c4]);
        }
        cp_commit();
    };

    float acc[2][4][4];
#pragma unroll
    for (int i = 0; i < 2; i++)
#pragma unroll
        for (int j = 0; j < 4; j++)
#pragma unroll
            for (int q = 0; q < 4; q++) acc[i][j][q] = 0.f;

    issue(0, 0);
    issue(1, 16);

    for (int kt = 0; kt < NKT; kt++) {
        if (kt == NKT - 1)
            asm volatile("cp.async.wait_group 0;" ::: "memory");
        else
            asm volatile("cp.async.wait_group 1;" ::: "memory");
        __syncthreads();
        if (kt + 2 < NKT) issue((kt + 2) % 3, (kt + 2) * 16);

        const float* As_ = smem + (kt % 3) * SS;
        const float* Bs_ = As_ + SA;
        float bs[2][2] = {{0.f, 0.f}, {0.f, 0.f}};
#pragma unroll
        for (int ks = 0; ks < 16; ks += 8) {
            uint32_t af[2][4], bf[4][2];
#pragma unroll
            for (int i = 0; i < 2; i++) {
                const int m = wm * 32 + i * 16 + g;
                af[i][0] = __float_as_uint(f2tf32(As_[m * 20 + ks + tg]));
                af[i][1] = __float_as_uint(f2tf32(As_[(m + 8) * 20 + ks + tg]));
                af[i][2] = __float_as_uint(f2tf32(As_[m * 20 + ks + tg + 4]));
                af[i][3] = __float_as_uint(f2tf32(As_[(m + 8) * 20 + ks + tg + 4]));
            }
#pragma unroll
            for (int j = 0; j < 4; j++) {
                const int col = wq * 32 + j * 8 + g;
                const float b0 = Bs_[(ks + tg) * 136 + col];
                const float b1 = Bs_[(ks + tg + 4) * 136 + col];
                bs[ks >> 3][0] += b0;
                bs[ks >> 3][1] += b1;
                bf[j][0] = __float_as_uint(f2tf32(b0));
                bf[j][1] = __float_as_uint(f2tf32(b1));
            }
#pragma unroll
            for (int i = 0; i < 2; i++)
#pragma unroll
                for (int j = 0; j < 4; j++) mma_tf32(acc[i][j], af[i], bf[j]);
        }
        // channel-sum contribution (wm==0 warps only; each covers distinct cols)
        if (wid < 4) {
#pragma unroll
            for (int s = 0; s < 2; s++)
#pragma unroll
                for (int r = 0; r < 2; r++) {
                    const float v = red_g(bs[s][r]);
                    if (lane < 4)
                        atomicAdd(&s_msum[kt * 16 + 8 * s + 4 * r + lane], v);
                }
        }
    }
    // write per-block channel sums
    __syncthreads();
    d_msum[((size_t)n * 32 + blockIdx.y) * 256 + tid] = s_msum[tid];

    // epilogue: relu + fp16 store
#pragma unroll
    for (int i = 0; i < 2; i++) {
        const int o = wm * 32 + i * 16 + g;
        const float bv0 = bias[o];
        const float bv1 = bias[o + 8];
#pragma unroll
        for (int j = 0; j < 4; j++) {
            const int px = p0 + wq * 32 + j * 8 + 2 * tg;
            *reinterpret_cast<__half2*>(&Cn[(size_t)o * HW + px]) =
                __floats2half2_rn(fmaxf(acc[i][j][0] + bv0, 0.f),
                                  fmaxf(acc[i][j][1] + bv0, 0.f));
            *reinterpret_cast<__half2*>(&Cn[(size_t)(o + 8) * HW + px]) =
                __floats2half2_rn(fmaxf(acc[i][j][2] + bv1, 0.f),
                                  fmaxf(acc[i][j][3] + bv1, 0.f));
        }
    }
}

// ---------------- K4b: out = Wcat @ ocat + cbias (tf32 mma, fp16 B operand) ----------------
// block 128o x 128px, 8 warps (2m x 4n), 3-stage cp.async, half B tiles.
__global__ void __launch_bounds__(256) k4b_kernel(
    const float* __restrict__ A, const float* __restrict__ bias,
    float* __restrict__ C) {
    constexpr int SA_B = 128 * 20 * 4;            // A stage bytes (float)
    constexpr int SB_B = 16 * 136 * 2;            // B stage bytes (half)
    constexpr int SS_B = SA_B + SB_B;
    constexpr int NKT = KCAT / 16;
    extern __shared__ char smemc[];

    const int o0 = blockIdx.x * 128;
    const int p0 = blockIdx.y * 128;
    const int n = blockIdx.z;
    const __half* Bn = d_ocat + (size_t)n * KCAT * HW;
    float* Cn = C + (size_t)n * MTOT * HW;

    const int tid = threadIdx.x;
    const int wid = tid >> 5, lane = tid & 31;
    const int wm = wid >> 2, wq = wid & 3;
    const int g = lane >> 2, tg = lane & 3;

    auto issue = [&](int s, int k0) {
        float* As_ = reinterpret_cast<float*>(smemc + s * SS_B);
        __half* Bs_ = reinterpret_cast<__half*>(smemc + s * SS_B + SA_B);
#pragma unroll
        for (int v = tid; v < 512; v += 256) {
            const int row = v >> 2, kq = (v & 3) << 2;
            cp16(&As_[row * 20 + kq], &A[(size_t)(o0 + row) * KCAT + k0 + kq]);
        }
        {
            const int row = tid >> 4, pb = (tid & 15) << 3;  // 8 halfs = 16 B
            cp16(&Bs_[row * 136 + pb], &Bn[(size_t)(k0 + row) * HW + p0 + pb]);
        }
        cp_commit();
    };

    float acc[4][4][4];
#pragma unroll
    for (int i = 0; i < 4; i++)
#pragma unroll
        for (int j = 0; j < 4; j++)
#pragma unroll
            for (int q = 0; q < 4; q++) acc[i][j][q] = 0.f;

    issue(0, 0);
    issue(1, 16);

    for (int kt = 0; kt < NKT; kt++) {
        if (kt == NKT - 1)
            asm volatile("cp.async.wait_group 0;" ::: "memory");
        else
            asm volatile("cp.async.wait_group 1;" ::: "memory");
        __syncthreads();
        if (kt + 2 < NKT) issue((kt + 2) % 3, (kt + 2) * 16);

        const float* As_ = reinterpret_cast<const float*>(smemc + (kt % 3) * SS_B);
        const __half* Bs_ = reinterpret_cast<const __half*>(smemc + (kt % 3) * SS_B + SA_B);
#pragma unroll
        for (int ks = 0; ks < 16; ks += 8) {
            uint32_t af[4][4], bf[4][2];
#pragma unroll
            for (int i = 0; i < 4; i++) {
                const int m = wm * 64 + i * 16 + g;
                af[i][0] = __float_as_uint(As_[m * 20 + ks + tg]);
                af[i][1] = __float_as_uint(As_[(m + 8) * 20 + ks + tg]);
                af[i][2] = __float_as_uint(As_[m * 20 + ks + tg + 4]);
                af[i][3] = __float_as_uint(As_[(m + 8) * 20 + ks + tg + 4]);
            }
#pragma unroll
            for (int j = 0; j < 4; j++) {
                const int col = wq * 32 + j * 8 + g;
                // half -> float is exact; half values are tf32-representable.
                bf[j][0] = __float_as_uint(__half2float(Bs_[(ks + tg) * 136 + col]));
                bf[j][1] = __float_as_uint(__half2float(Bs_[(ks + tg + 4) * 136 + col]));
            }
#pragma unroll
            for (int i = 0; i < 4; i++)
#pragma unroll
                for (int j = 0; j < 4; j++) mma_tf32(acc[i][j], af[i], bf[j]);
        }
    }
    // epilogue
#pragma unroll
    for (int i = 0; i < 4; i++) {
        const int o = o0 + wm * 64 + i * 16 + g;
        const float bv0 = bias[o];
        const float bv1 = bias[o + 8];
#pragma unroll
        for (int j = 0; j < 4; j++) {
            const int px = p0 + wq * 32 + j * 8 + 2 * tg;
            *reinterpret_cast<float2*>(&Cn[(size_t)o * HW + px]) =
                make_float2(acc[i][j][0] + bv0, acc[i][j][1] + bv0);
            *reinterpret_cast<float2*>(&Cn[(size_t)(o + 8) * HW + px]) =
                make_float2(acc[i][j][2] + bv1, acc[i][j][3] + bv1);
        }
    }
}

// ---------------- K4a: depthwise convs, fp16 in/out, 4 px/thread ----------------
__global__ void __launch_bounds__(256) dw_kernel() {
    const int c = blockIdx.x;  // 64
    const int n = blockIdx.y;  // 32
    __shared__ float sm[72 * 72];
    __shared__ float kk[43];
    const int tid = threadIdx.x;
    for (int i = tid; i < 72 * 72; i += 256) sm[i] = 0.f;
    __syncthreads();
    const __half2* fb2 = reinterpret_cast<const __half2*>(
        d_f + ((size_t)n * CMC + c) * HW);
    for (int i = tid; i < HW / 2; i += 256) {
        const float2 v = __half22float2(fb2[i]);
        const int idx = i * 2;
        const int base = ((idx >> 6) + 4) * 72 + (idx & 63) + 4;
        sm[base] = v.x;
        sm[base + 1] = v.y;
    }
    if (tid < 43) kk[tid] = d_ker[((size_t)n * CMC + c) * 43 + tid];
    __syncthreads();

    __half* o1 = d_ocat + ((size_t)n * KCAT + c) * HW;
    __half* o2 = o1 + (size_t)64 * HW;
    __half* o3 = o1 + (size_t)128 * HW;

    const int w0 = (tid & 15) * 4;

#pragma unroll
    for (int pass = 0; pass < 4; pass++) {
        const int h = pass * 16 + (tid >> 4);
        float s1[4] = {0.f, 0.f, 0.f, 0.f};
        float s2[4] = {0.f, 0.f, 0.f, 0.f};
        float s3[4] = {0.f, 0.f, 0.f, 0.f};
        float rv[12];

        auto loadrow = [&](int ri) {
            const float4 a = *reinterpret_cast<const float4*>(&sm[ri * 72 + w0]);
            const float4 b = *reinterpret_cast<const float4*>(&sm[ri * 72 + w0 + 4]);
            const float4 d = *reinterpret_cast<const float4*>(&sm[ri * 72 + w0 + 8]);
            rv[0] = a.x; rv[1] = a.y; rv[2] = a.z; rv[3] = a.w;
            rv[4] = b.x; rv[5] = b.y; rv[6] = b.z; rv[7] = b.w;
            rv[8] = d.x; rv[9] = d.y; rv[10] = d.z; rv[11] = d.w;
        };
        auto b1row = [&](int dy) {
#pragma unroll
            for (int dx = 0; dx < 5; dx++) {
                const float kv = kk[dy * 5 + dx];
#pragma unroll
                for (int px = 0; px < 4; px++) s1[px] = fmaf(kv, rv[px + dx + 2], s1[px]);
            }
        };
        auto b2row = [&](int dy2) {
#pragma unroll
            for (int dx = 0; dx < 3; dx++) {
                const float kv = kk[25 + dy2 * 3 + dx];
#pragma unroll
                for (int px = 0; px < 4; px++) s2[px] = fmaf(kv, rv[px + 2 * dx + 2], s2[px]);
            }
        };
        auto b3row = [&](int dy4) {
#pragma unroll
            for (int dx = 0; dx < 3; dx++) {
                const float kv = kk[34 + dy4 * 3 + dx];
#pragma unroll
                for (int px = 0; px < 4; px++) s3[px] = fmaf(kv, rv[px + 4 * dx], s3[px]);
            }
        };

        loadrow(h);     b3row(0);
        loadrow(h + 2); b1row(0); b2row(0);
        loadrow(h + 3); b1row(1);
        loadrow(h + 4); b1row(2); b2row(1); b3row(1);
        loadrow(h + 5); b1row(3);
        loadrow(h + 6); b1row(4); b2row(2);
        loadrow(h + 8); b3row(2);

        const int i2 = (h * 64 + w0) >> 1;
        reinterpret_cast<__half2*>(o1)[i2]     = __floats2half2_rn(s1[0], s1[1]);
        reinterpret_cast<__half2*>(o1)[i2 + 1] = __floats2half2_rn(s1[2], s1[3]);
        reinterpret_cast<__half2*>(o2)[i2]     = __floats2half2_rn(s2[0], s2[1]);
        reinterpret_cast<__half2*>(o2)[i2 + 1] = __floats2half2_rn(s2[2], s2[3]);
        reinterpret_cast<__half2*>(o3)[i2]     = __floats2half2_rn(s3[0], s3[1]);
        reinterpret_cast<__half2*>(o3)[i2 + 1] = __floats2half2_rn(s3[2], s3[3]);
    }
}

// ---------------- host launch ----------------
extern "C" void kernel_launch(void* const* d_in, const int* in_sizes, int n_in,
                              void* d_out, int out_size) {
    (void)in_sizes; (void)n_in; (void)out_size;
    const float* x      = (const float*)d_in[0];
    const float* conv_w = (const float*)d_in[1];
    const float* conv_b = (const float*)d_in[2];
    const float* ckw    = (const float*)d_in[3];
    const float* ckb    = (const float*)d_in[4];
    const float* ck2w   = (const float*)d_in[5];
    const float* ck2b   = (const float*)d_in[6];
    const float* ckd4w  = (const float*)d_in[7];
    const float* ckd4b  = (const float*)d_in[8];
    const float* kw     = (const float*)d_in[9];
    const float* kb     = (const float*)d_in[10];
    const float* k2w    = (const float*)d_in[11];
    const float* k2b    = (const float*)d_in[12];
    const float* kd4w   = (const float*)d_in[13];
    const float* kd4b   = (const float*)d_in[14];
    const float* fuse_w = (const float*)d_in[15];
    const float* fuse_b = (const float*)d_in[16];
    const float* fc_w   = (const float*)d_in[17];
    const float* fc_b   = (const float*)d_in[18];
    float* out = (float*)d_out;

    void *p_Wcat = nullptr, *p_cbias = nullptr;
    cudaGetSymbolAddress(&p_Wcat, d_Wcat);
    cudaGetSymbolAddress(&p_cbias, d_cbias);

    constexpr int SMEM_K3  = 3 * (64 * 20 + 16 * 136) * 4 + 256 * 4;      // 42496 B
    constexpr int SMEM_K4B = 3 * (128 * 20 * 4 + 16 * 136 * 2);           // 43776 B
    cudaFuncSetAttribute(k3_kernel, cudaFuncAttributeMaxDynamicSharedMemorySize, SMEM_K3);
    cudaFuncSetAttribute(k4b_kernel, cudaFuncAttributeMaxDynamicSharedMemorySize, SMEM_K4B);

    // K2b: collapsed fuse+fc weights (independent of x)
    wcat_kernel<<<(MTOT * KCAT + MTOT + 255) / 256, 256>>>(fc_w, fc_b, fuse_w, fuse_b);
    // K3: f = relu(1x1 conv 256->64) + fused per-block channel sums of x
    k3_kernel<<<dim3(1, HW / 128, NB), 256, SMEM_K3>>>(conv_w, x, conv_b);
    // mean = reduce(partials)
    mean_reduce_kernel<<<NB * CIN / 256, 256>>>();
    // K2a: g + dynamic depthwise kernels (needs mean)
    gker_kernel<<<8, 256>>>(conv_w, conv_b, ckw, ckb, ck2w, ck2b, ckd4w, ckd4b,
                            kw, kb, k2w, k2b, kd4w, kd4b);
    // K4a: dynamic depthwise (3 branches) -> ocat (fp16)
    dw_kernel<<<dim3(CMC, NB), 256>>>();
    // K4b: out = Wcat @ ocat + cbias (tf32 mma, fp16 B tiles)
    k4b_kernel<<<dim3(MTOT / 128, HW / 128, NB), 256, SMEM_K4B>>>(
        (const float*)p_Wcat, (const float*)p_cbias, out);
}

// round 10
// speedup vs baseline: 1.7232x; 1.7232x over previous
#include <cuda_runtime.h>
#include <cuda_fp16.h>
#include <cstdint>
#include <cstddef>

#define HW   4096
#define NB   32
#define CIN  256
#define CMC  64
#define MTOT 384
#define KCAT 192

// ---------------- scratch (static device globals; no allocation) ----------------
__device__ float  d_mean[NB * CIN];
__device__ float  d_ker[NB * CMC * 43];
__device__ float  d_Wcat[MTOT * KCAT];                    // tf32-rounded
__device__ float  d_cbias[MTOT];
__device__ __half d_f[(size_t)NB * CMC * HW];             // 16.8 MB (fp16)
__device__ __half d_ocat[(size_t)NB * KCAT * HW];         // 50.3 MB (fp16)

// ---------------- helpers ----------------
__device__ __forceinline__ float f2tf32(float f) {
    uint32_t r;
    asm("cvt.rna.tf32.f32 %0, %1;" : "=r"(r) : "f"(f));
    return __uint_as_float(r);
}
__device__ __forceinline__ void mma_tf32(float c[4], const uint32_t a[4],
                                         const uint32_t b[2]) {
    asm volatile(
        "mma.sync.aligned.m16n8k8.row.col.f32.tf32.tf32.f32 "
        "{%0,%1,%2,%3}, {%4,%5,%6,%7}, {%8,%9}, {%0,%1,%2,%3};"
        : "+f"(c[0]), "+f"(c[1]), "+f"(c[2]), "+f"(c[3])
        : "r"(a[0]), "r"(a[1]), "r"(a[2]), "r"(a[3]), "r"(b[0]), "r"(b[1]));
}
__device__ __forceinline__ void cp16(void* sptr, const void* g) {
    unsigned sa = (unsigned)__cvta_generic_to_shared(sptr);
    asm volatile("cp.async.cg.shared.global [%0], [%1], 16;" :: "r"(sa), "l"(g));
}
__device__ __forceinline__ void cp_commit() {
    asm volatile("cp.async.commit_group;" ::: "memory");
}

// ---------------- K1: per-(n,c) spatial mean ----------------
__global__ void __launch_bounds__(256) mean_kernel(const float* __restrict__ x) {
    const int idx = blockIdx.x;
    const float4* p = reinterpret_cast<const float4*>(x + (size_t)idx * HW);
    float s = 0.f;
#pragma unroll
    for (int i = 0; i < 4; i++) {
        float4 v = p[threadIdx.x + i * 256];
        s += (v.x + v.y) + (v.z + v.w);
    }
#pragma unroll
    for (int o = 16; o; o >>= 1) s += __shfl_down_sync(0xffffffffu, s, o);
    __shared__ float ws[8];
    if ((threadIdx.x & 31) == 0) ws[threadIdx.x >> 5] = s;
    __syncthreads();
    if (threadIdx.x < 8) {
        float t = ws[threadIdx.x];
#pragma unroll
        for (int o = 4; o; o >>= 1) t += __shfl_down_sync(0xffu, t, o);
        if (threadIdx.x == 0) d_mean[idx] = t * (1.f / 4096.f);
    }
}

// ---------------- K2a: g + dynamic kernels (warp per (n,c)) ----------------
__global__ void __launch_bounds__(256) gker_kernel(
    const float* __restrict__ conv_w, const float* __restrict__ conv_b,
    const float* __restrict__ ckw, const float* __restrict__ ckb,
    const float* __restrict__ ck2w, const float* __restrict__ ck2b,
    const float* __restrict__ ckd4w, const float* __restrict__ ckd4b,
    const float* __restrict__ kw, const float* __restrict__ kb,
    const float* __restrict__ k2w, const float* __restrict__ k2b,
    const float* __restrict__ kd4w, const float* __restrict__ kd4b) {
    const int t = blockIdx.x * 8 + (threadIdx.x >> 5);  // (n, c), 2048 warps
    const int lane = threadIdx.x & 31;
    const int n = t >> 6, c = t & 63;
    const float* mrow = &d_mean[n * CIN];
    const float* wrow = &conv_w[c * CIN];
    float s = 0.f;
#pragma unroll
    for (int i = 0; i < 8; i++) {
        const int k = lane + 32 * i;
        s = fmaf(mrow[k], wrow[k], s);
    }
#pragma unroll
    for (int o = 16; o; o >>= 1) s += __shfl_xor_sync(0xffffffffu, s, o);
    const float g = fmaxf(s + conv_b[c], 0.f);
    float* kp = &d_ker[(size_t)t * 43];
    if (lane < 25) kp[lane] = fmaf(*ckw, fmaf(g, kw[lane], kb[lane]), *ckb);
    if (lane < 9) {
        kp[25 + lane] = fmaf(*ck2w, fmaf(g, k2w[lane], k2b[lane]), *ck2b);
        kp[34 + lane] = fmaf(*ckd4w, fmaf(g, kd4w[lane], kd4b[lane]), *ckd4b);
    }
}

// ---------------- K2b: collapsed weights Wcat (tf32-rounded) and cbias ----------------
__global__ void __launch_bounds__(256) wcat_kernel(
    const float* __restrict__ fc_w, const float* __restrict__ fc_b,
    const float* __restrict__ fuse_w, const float* __restrict__ fuse_b) {
    const int m = blockIdx.x * 256 + threadIdx.x;
    if (m < MTOT * KCAT) {
        const int o = m / KCAT, cs = m % KCAT;
        const int b = cs >> 6, c = cs & 63;
        const float* fcr = &fc_w[o * 384 + b * 128];
        float s = 0.f;
#pragma unroll 4
        for (int j = 0; j < 128; j++) s = fmaf(fcr[j], fuse_w[j * 64 + c], s);
        d_Wcat[m] = f2tf32(s);
    } else {
        const int o = m - MTOT * KCAT;
        if (o < MTOT) {
            float s = fc_b[o];
            for (int j = 0; j < 384; j++)
                s = fmaf(fc_w[o * 384 + j], fuse_b[j & 127], s);
            d_cbias[o] = s;
        }
    }
}

// ---------------- K3: f = relu(conv_w @ x + b), tf32 mma, fp16 out ----------------
// block 64o x 128px, 8 warps (2m x 4n), 3-stage cp.async pipeline.
__global__ void __launch_bounds__(256) k3_kernel(
    const float* __restrict__ A, const float* __restrict__ B,
    const float* __restrict__ bias) {
    constexpr int SA = 64 * 20, SB = 16 * 136, SS = SA + SB;  // floats
    constexpr int NKT = CIN / 16;
    extern __shared__ float smem[];

    const int p0 = blockIdx.y * 128;
    const int n = blockIdx.z;
    const float* Bn = B + (size_t)n * CIN * HW;
    __half* Cn = d_f + (size_t)n * CMC * HW;

    const int tid = threadIdx.x;
    const int wid = tid >> 5, lane = tid & 31;
    const int wm = wid >> 2, wq = wid & 3;
    const int g = lane >> 2, tg = lane & 3;

    auto issue = [&](int s, int k0) {
        float* As_ = smem + s * SS;
        float* Bs_ = As_ + SA;
        {
            const int row = tid >> 2, kq = (tid & 3) << 2;
            cp16(&As_[row * 20 + kq], &A[(size_t)row * CIN + k0 + kq]);
        }
#pragma unroll
        for (int v = tid; v < 512; v += 256) {
            const int row = v >> 5, c4 = (v & 31) << 2;
            cp16(&Bs_[row * 136 + c4], &Bn[(size_t)(k0 + row) * HW + p0 + c4]);
        }
        cp_commit();
    };

    float acc[2][4][4];
#pragma unroll
    for (int i = 0; i < 2; i++)
#pragma unroll
        for (int j = 0; j < 4; j++)
#pragma unroll
            for (int q = 0; q < 4; q++) acc[i][j][q] = 0.f;

    issue(0, 0);
    issue(1, 16);

    for (int kt = 0; kt < NKT; kt++) {
        if (kt == NKT - 1)
            asm volatile("cp.async.wait_group 0;" ::: "memory");
        else
            asm volatile("cp.async.wait_group 1;" ::: "memory");
        __syncthreads();
        if (kt + 2 < NKT) issue((kt + 2) % 3, (kt + 2) * 16);

        const float* As_ = smem + (kt % 3) * SS;
        const float* Bs_ = As_ + SA;
#pragma unroll
        for (int ks = 0; ks < 16; ks += 8) {
            uint32_t af[2][4], bf[4][2];
#pragma unroll
            for (int i = 0; i < 2; i++) {
                const int m = wm * 32 + i * 16 + g;
                af[i][0] = __float_as_uint(f2tf32(As_[m * 20 + ks + tg]));
                af[i][1] = __float_as_uint(f2tf32(As_[(m + 8) * 20 + ks + tg]));
                af[i][2] = __float_as_uint(f2tf32(As_[m * 20 + ks + tg + 4]));
                af[i][3] = __float_as_uint(f2tf32(As_[(m + 8) * 20 + ks + tg + 4]));
            }
#pragma unroll
            for (int j = 0; j < 4; j++) {
                const int col = wq * 32 + j * 8 + g;
                bf[j][0] = __float_as_uint(f2tf32(Bs_[(ks + tg) * 136 + col]));
                bf[j][1] = __float_as_uint(f2tf32(Bs_[(ks + tg + 4) * 136 + col]));
            }
#pragma unroll
            for (int i = 0; i < 2; i++)
#pragma unroll
                for (int j = 0; j < 4; j++) mma_tf32(acc[i][j], af[i], bf[j]);
        }
    }
    // epilogue: relu + fp16 store
#pragma unroll
    for (int i = 0; i < 2; i++) {
        const int o = wm * 32 + i * 16 + g;
        const float bv0 = bias[o];
        const float bv1 = bias[o + 8];
#pragma unroll
        for (int j = 0; j < 4; j++) {
            const int px = p0 + wq * 32 + j * 8 + 2 * tg;
            *reinterpret_cast<__half2*>(&Cn[(size_t)o * HW + px]) =
                __floats2half2_rn(fmaxf(acc[i][j][0] + bv0, 0.f),
                                  fmaxf(acc[i][j][1] + bv0, 0.f));
            *reinterpret_cast<__half2*>(&Cn[(size_t)(o + 8) * HW + px]) =
                __floats2half2_rn(fmaxf(acc[i][j][2] + bv1, 0.f),
                                  fmaxf(acc[i][j][3] + bv1, 0.f));
        }
    }
}

// ---------------- K4b: out = Wcat @ ocat + cbias (tf32 mma, fp16 B operand) ----------------
// block 128o x 128px, 8 warps (2m x 4n), 3-stage cp.async, half B tiles.
__global__ void __launch_bounds__(256) k4b_kernel(
    const float* __restrict__ A, const float* __restrict__ bias,
    float* __restrict__ C) {
    constexpr int SA_B = 128 * 20 * 4;            // A stage bytes (float)
    constexpr int SB_B = 16 * 136 * 2;            // B stage bytes (half)
    constexpr int SS_B = SA_B + SB_B;
    constexpr int NKT = KCAT / 16;
    extern __shared__ char smemc[];

    const int o0 = blockIdx.x * 128;
    const int p0 = blockIdx.y * 128;
    const int n = blockIdx.z;
    const __half* Bn = d_ocat + (size_t)n * KCAT * HW;
    float* Cn = C + (size_t)n * MTOT * HW;

    const int tid = threadIdx.x;
    const int wid = tid >> 5, lane = tid & 31;
    const int wm = wid >> 2, wq = wid & 3;
    const int g = lane >> 2, tg = lane & 3;

    auto issue = [&](int s, int k0) {
        float* As_ = reinterpret_cast<float*>(smemc + s * SS_B);
        __half* Bs_ = reinterpret_cast<__half*>(smemc + s * SS_B + SA_B);
#pragma unroll
        for (int v = tid; v < 512; v += 256) {
            const int row = v >> 2, kq = (v & 3) << 2;
            cp16(&As_[row * 20 + kq], &A[(size_t)(o0 + row) * KCAT + k0 + kq]);
        }
        {
            const int row = tid >> 4, pb = (tid & 15) << 3;  // 8 halfs = 16 B
            cp16(&Bs_[row * 136 + pb], &Bn[(size_t)(k0 + row) * HW + p0 + pb]);
        }
        cp_commit();
    };

    float acc[4][4][4];
#pragma unroll
    for (int i = 0; i < 4; i++)
#pragma unroll
        for (int j = 0; j < 4; j++)
#pragma unroll
            for (int q = 0; q < 4; q++) acc[i][j][q] = 0.f;

    issue(0, 0);
    issue(1, 16);

    for (int kt = 0; kt < NKT; kt++) {
        if (kt == NKT - 1)
            asm volatile("cp.async.wait_group 0;" ::: "memory");
        else
            asm volatile("cp.async.wait_group 1;" ::: "memory");
        __syncthreads();
        if (kt + 2 < NKT) issue((kt + 2) % 3, (kt + 2) * 16);

        const float* As_ = reinterpret_cast<const float*>(smemc + (kt % 3) * SS_B);
        const __half* Bs_ = reinterpret_cast<const __half*>(smemc + (kt % 3) * SS_B + SA_B);
#pragma unroll
        for (int ks = 0; ks < 16; ks += 8) {
            uint32_t af[4][4], bf[4][2];
#pragma unroll
            for (int i = 0; i < 4; i++) {
                const int m = wm * 64 + i * 16 + g;
                af[i][0] = __float_as_uint(As_[m * 20 + ks + tg]);
                af[i][1] = __float_as_uint(As_[(m + 8) * 20 + ks + tg]);
                af[i][2] = __float_as_uint(As_[m * 20 + ks + tg + 4]);
                af[i][3] = __float_as_uint(As_[(m + 8) * 20 + ks + tg + 4]);
            }
#pragma unroll
            for (int j = 0; j < 4; j++) {
                const int col = wq * 32 + j * 8 + g;
                // half -> float is exact; half values are tf32-representable.
                bf[j][0] = __float_as_uint(__half2float(Bs_[(ks + tg) * 136 + col]));
                bf[j][1] = __float_as_uint(__half2float(Bs_[(ks + tg + 4) * 136 + col]));
            }
#pragma unroll
            for (int i = 0; i < 4; i++)
#pragma unroll
                for (int j = 0; j < 4; j++) mma_tf32(acc[i][j], af[i], bf[j]);
        }
    }
    // epilogue
#pragma unroll
    for (int i = 0; i < 4; i++) {
        const int o = o0 + wm * 64 + i * 16 + g;
        const float bv0 = bias[o];
        const float bv1 = bias[o + 8];
#pragma unroll
        for (int j = 0; j < 4; j++) {
            const int px = p0 + wq * 32 + j * 8 + 2 * tg;
            *reinterpret_cast<float2*>(&Cn[(size_t)o * HW + px]) =
                make_float2(acc[i][j][0] + bv0, acc[i][j][1] + bv0);
            *reinterpret_cast<float2*>(&Cn[(size_t)(o + 8) * HW + px]) =
                make_float2(acc[i][j][2] + bv1, acc[i][j][3] + bv1);
        }
    }
}

// ---------------- K4a: depthwise convs, fp16 in/out, 4 px/thread ----------------
__global__ void __launch_bounds__(256) dw_kernel() {
    const int c = blockIdx.x;  // 64
    const int n = blockIdx.y;  // 32
    __shared__ float sm[72 * 72];
    __shared__ float kk[43];
    const int tid = threadIdx.x;
    for (int i = tid; i < 72 * 72; i += 256) sm[i] = 0.f;
    __syncthreads();
    const __half2* fb2 = reinterpret_cast<const __half2*>(
        d_f + ((size_t)n * CMC + c) * HW);
    for (int i = tid; i < HW / 2; i += 256) {
        const float2 v = __half22float2(fb2[i]);
        const int idx = i * 2;
        const int base = ((idx >> 6) + 4) * 72 + (idx & 63) + 4;
        sm[base] = v.x;
        sm[base + 1] = v.y;
    }
    if (tid < 43) kk[tid] = d_ker[((size_t)n * CMC + c) * 43 + tid];
    __syncthreads();

    __half* o1 = d_ocat + ((size_t)n * KCAT + c) * HW;
    __half* o2 = o1 + (size_t)64 * HW;
    __half* o3 = o1 + (size_t)128 * HW;

    const int w0 = (tid & 15) * 4;

#pragma unroll
    for (int pass = 0; pass < 4; pass++) {
        const int h = pass * 16 + (tid >> 4);
        float s1[4] = {0.f, 0.f, 0.f, 0.f};
        float s2[4] = {0.f, 0.f, 0.f, 0.f};
        float s3[4] = {0.f, 0.f, 0.f, 0.f};
        float rv[12];

        auto loadrow = [&](int ri) {
            const float4 a = *reinterpret_cast<const float4*>(&sm[ri * 72 + w0]);
            const float4 b = *reinterpret_cast<const float4*>(&sm[ri * 72 + w0 + 4]);
            const float4 d = *reinterpret_cast<const float4*>(&sm[ri * 72 + w0 + 8]);
            rv[0] = a.x; rv[1] = a.y; rv[2] = a.z; rv[3] = a.w;
            rv[4] = b.x; rv[5] = b.y; rv[6] = b.z; rv[7] = b.w;
            rv[8] = d.x; rv[9] = d.y; rv[10] = d.z; rv[11] = d.w;
        };
        auto b1row = [&](int dy) {
#pragma unroll
            for (int dx = 0; dx < 5; dx++) {
                const float kv = kk[dy * 5 + dx];
#pragma unroll
                for (int px = 0; px < 4; px++) s1[px] = fmaf(kv, rv[px + dx + 2], s1[px]);
            }
        };
        auto b2row = [&](int dy2) {
#pragma unroll
            for (int dx = 0; dx < 3; dx++) {
                const float kv = kk[25 + dy2 * 3 + dx];
#pragma unroll
                for (int px = 0; px < 4; px++) s2[px] = fmaf(kv, rv[px + 2 * dx + 2], s2[px]);
            }
        };
        auto b3row = [&](int dy4) {
#pragma unroll
            for (int dx = 0; dx < 3; dx++) {
                const float kv = kk[34 + dy4 * 3 + dx];
#pragma unroll
                for (int px = 0; px < 4; px++) s3[px] = fmaf(kv, rv[px + 4 * dx], s3[px]);
            }
        };

        loadrow(h);     b3row(0);
        loadrow(h + 2); b1row(0); b2row(0);
        loadrow(h + 3); b1row(1);
        loadrow(h + 4); b1row(2); b2row(1); b3row(1);
        loadrow(h + 5); b1row(3);
        loadrow(h + 6); b1row(4); b2row(2);
        loadrow(h + 8); b3row(2);

        const int i2 = (h * 64 + w0) >> 1;
        reinterpret_cast<__half2*>(o1)[i2]     = __floats2half2_rn(s1[0], s1[1]);
        reinterpret_cast<__half2*>(o1)[i2 + 1] = __floats2half2_rn(s1[2], s1[3]);
        reinterpret_cast<__half2*>(o2)[i2]     = __floats2half2_rn(s2[0], s2[1]);
        reinterpret_cast<__half2*>(o2)[i2 + 1] = __floats2half2_rn(s2[2], s2[3]);
        reinterpret_cast<__half2*>(o3)[i2]     = __floats2half2_rn(s3[0], s3[1]);
        reinterpret_cast<__half2*>(o3)[i2 + 1] = __floats2half2_rn(s3[2], s3[3]);
    }
}

// ---------------- host launch ----------------
extern "C" void kernel_launch(void* const* d_in, const int* in_sizes, int n_in,
                              void* d_out, int out_size) {
    (void)in_sizes; (void)n_in; (void)out_size;
    const float* x      = (const float*)d_in[0];
    const float* conv_w = (const float*)d_in[1];
    const float* conv_b = (const float*)d_in[2];
    const float* ckw    = (const float*)d_in[3];
    const float* ckb    = (const float*)d_in[4];
    const float* ck2w   = (const float*)d_in[5];
    const float* ck2b   = (const float*)d_in[6];
    const float* ckd4w  = (const float*)d_in[7];
    const float* ckd4b  = (const float*)d_in[8];
    const float* kw     = (const float*)d_in[9];
    const float* kb     = (const float*)d_in[10];
    const float* k2w    = (const float*)d_in[11];
    const float* k2b    = (const float*)d_in[12];
    const float* kd4w   = (const float*)d_in[13];
    const float* kd4b   = (const float*)d_in[14];
    const float* fuse_w = (const float*)d_in[15];
    const float* fuse_b = (const float*)d_in[16];
    const float* fc_w   = (const float*)d_in[17];
    const float* fc_b   = (const float*)d_in[18];
    float* out = (float*)d_out;

    void *p_Wcat = nullptr, *p_cbias = nullptr;
    cudaGetSymbolAddress(&p_Wcat, d_Wcat);
    cudaGetSymbolAddress(&p_cbias, d_cbias);

    constexpr int SMEM_K3  = 3 * (64 * 20 + 16 * 136) * 4;                // 41472 B
    constexpr int SMEM_K4B = 3 * (128 * 20 * 4 + 16 * 136 * 2);           // 43776 B
    cudaFuncSetAttribute(k3_kernel, cudaFuncAttributeMaxDynamicSharedMemorySize, SMEM_K3);
    cudaFuncSetAttribute(k4b_kernel, cudaFuncAttributeMaxDynamicSharedMemorySize, SMEM_K4B);

    // K1: spatial means (separate pass — the fused version regressed)
    mean_kernel<<<NB * CIN, 256>>>(x);
    // K2a: g + dynamic depthwise kernels (warp-parallel reduction)
    gker_kernel<<<256, 256>>>(conv_w, conv_b, ckw, ckb, ck2w, ck2b, ckd4w, ckd4b,
                              kw, kb, k2w, k2b, kd4w, kd4b);
    // K2b: collapsed fuse+fc weights
    wcat_kernel<<<(MTOT * KCAT + MTOT + 255) / 256, 256>>>(fc_w, fc_b, fuse_w, fuse_b);
    // K3: f = relu(1x1 conv 256->64), tf32 mma, fp16 out
    k3_kernel<<<dim3(1, HW / 128, NB), 256, SMEM_K3>>>(conv_w, x, conv_b);
    // K4a: dynamic depthwise (3 branches) -> ocat (fp16)
    dw_kernel<<<dim3(CMC, NB), 256>>>();
    // K4b: out = Wcat @ ocat + cbias (tf32 mma, fp16 B tiles)
    k4b_kernel<<<dim3(MTOT / 128, HW / 128, NB), 256, SMEM_K4B>>>(
        (const float*)p_Wcat, (const float*)p_cbias, out);
}

// round 11
// speedup vs baseline: 1.9848x; 1.1519x over previous
#include <cuda_runtime.h>
#include <cuda_fp16.h>
#include <cstdint>
#include <cstddef>

#define HW   4096
#define NB   32
#define CIN  256
#define CMC  64
#define MTOT 384
#define KCAT 192

// ---------------- scratch (static device globals; no allocation) ----------------
__device__ float  d_mean[NB * CIN];
__device__ float  d_ker[NB * CMC * 43];
__device__ __half d_Wcat[MTOT * KCAT];                    // fp16 (10-bit mantissa = tf32)
__device__ float  d_cbias[MTOT];
__device__ __half d_f[(size_t)NB * CMC * HW];             // 16.8 MB (fp16)
__device__ __half d_ocat[(size_t)NB * KCAT * HW];         // 50.3 MB (fp16)

// ---------------- helpers ----------------
__device__ __forceinline__ float f2tf32(float f) {
    uint32_t r;
    asm("cvt.rna.tf32.f32 %0, %1;" : "=r"(r) : "f"(f));
    return __uint_as_float(r);
}
__device__ __forceinline__ void mma_tf32(float c[4], const uint32_t a[4],
                                         const uint32_t b[2]) {
    asm volatile(
        "mma.sync.aligned.m16n8k8.row.col.f32.tf32.tf32.f32 "
        "{%0,%1,%2,%3}, {%4,%5,%6,%7}, {%8,%9}, {%0,%1,%2,%3};"
        : "+f"(c[0]), "+f"(c[1]), "+f"(c[2]), "+f"(c[3])
        : "r"(a[0]), "r"(a[1]), "r"(a[2]), "r"(a[3]), "r"(b[0]), "r"(b[1]));
}
__device__ __forceinline__ void mma_f16(float c[4], const uint32_t a[4],
                                        const uint32_t b[2]) {
    asm volatile(
        "mma.sync.aligned.m16n8k16.row.col.f32.f16.f16.f32 "
        "{%0,%1,%2,%3}, {%4,%5,%6,%7}, {%8,%9}, {%0,%1,%2,%3};"
        : "+f"(c[0]), "+f"(c[1]), "+f"(c[2]), "+f"(c[3])
        : "r"(a[0]), "r"(a[1]), "r"(a[2]), "r"(a[3]), "r"(b[0]), "r"(b[1]));
}
__device__ __forceinline__ void cp16(void* sptr, const void* g) {
    unsigned sa = (unsigned)__cvta_generic_to_shared(sptr);
    asm volatile("cp.async.cg.shared.global [%0], [%1], 16;" :: "r"(sa), "l"(g));
}
__device__ __forceinline__ void cp_commit() {
    asm volatile("cp.async.commit_group;" ::: "memory");
}

// ---------------- K1: per-(n,c) spatial mean ----------------
__global__ void __launch_bounds__(256) mean_kernel(const float* __restrict__ x) {
    const int idx = blockIdx.x;
    const float4* p = reinterpret_cast<const float4*>(x + (size_t)idx * HW);
    float s = 0.f;
#pragma unroll
    for (int i = 0; i < 4; i++) {
        float4 v = p[threadIdx.x + i * 256];
        s += (v.x + v.y) + (v.z + v.w);
    }
#pragma unroll
    for (int o = 16; o; o >>= 1) s += __shfl_down_sync(0xffffffffu, s, o);
    __shared__ float ws[8];
    if ((threadIdx.x & 31) == 0) ws[threadIdx.x >> 5] = s;
    __syncthreads();
    if (threadIdx.x < 8) {
        float t = ws[threadIdx.x];
#pragma unroll
        for (int o = 4; o; o >>= 1) t += __shfl_down_sync(0xffu, t, o);
        if (threadIdx.x == 0) d_mean[idx] = t * (1.f / 4096.f);
    }
}

// ---------------- K2a: g + dynamic kernels (warp per (n,c)) ----------------
__global__ void __launch_bounds__(256) gker_kernel(
    const float* __restrict__ conv_w, const float* __restrict__ conv_b,
    const float* __restrict__ ckw, const float* __restrict__ ckb,
    const float* __restrict__ ck2w, const float* __restrict__ ck2b,
    const float* __restrict__ ckd4w, const float* __restrict__ ckd4b,
    const float* __restrict__ kw, const float* __restrict__ kb,
    const float* __restrict__ k2w, const float* __restrict__ k2b,
    const float* __restrict__ kd4w, const float* __restrict__ kd4b) {
    const int t = blockIdx.x * 8 + (threadIdx.x >> 5);  // (n, c), 2048 warps
    const int lane = threadIdx.x & 31;
    const int n = t >> 6, c = t & 63;
    const float* mrow = &d_mean[n * CIN];
    const float* wrow = &conv_w[c * CIN];
    float s = 0.f;
#pragma unroll
    for (int i = 0; i < 8; i++) {
        const int k = lane + 32 * i;
        s = fmaf(mrow[k], wrow[k], s);
    }
#pragma unroll
    for (int o = 16; o; o >>= 1) s += __shfl_xor_sync(0xffffffffu, s, o);
    const float g = fmaxf(s + conv_b[c], 0.f);
    float* kp = &d_ker[(size_t)t * 43];
    if (lane < 25) kp[lane] = fmaf(*ckw, fmaf(g, kw[lane], kb[lane]), *ckb);
    if (lane < 9) {
        kp[25 + lane] = fmaf(*ck2w, fmaf(g, k2w[lane], k2b[lane]), *ck2b);
        kp[34 + lane] = fmaf(*ckd4w, fmaf(g, kd4w[lane], kd4b[lane]), *ckd4b);
    }
}

// ---------------- K2b: collapsed weights Wcat (fp16) and cbias ----------------
__global__ void __launch_bounds__(256) wcat_kernel(
    const float* __restrict__ fc_w, const float* __restrict__ fc_b,
    const float* __restrict__ fuse_w, const float* __restrict__ fuse_b) {
    const int m = blockIdx.x * 256 + threadIdx.x;
    if (m < MTOT * KCAT) {
        const int o = m / KCAT, cs = m % KCAT;
        const int b = cs >> 6, c = cs & 63;
        const float* fcr = &fc_w[o * 384 + b * 128];
        float s = 0.f;
#pragma unroll 4
        for (int j = 0; j < 128; j++) s = fmaf(fcr[j], fuse_w[j * 64 + c], s);
        d_Wcat[m] = __float2half_rn(s);
    } else {
        const int o = m - MTOT * KCAT;
        if (o < MTOT) {
            float s = fc_b[o];
            for (int j = 0; j < 384; j++)
                s = fmaf(fc_w[o * 384 + j], fuse_b[j & 127], s);
            d_cbias[o] = s;
        }
    }
}

// ---------------- K3: f = relu(conv_w @ x + b), tf32 mma, fp16 out ----------------
// block 64o x 128px, 8 warps (2m x 4n), 3-stage cp.async pipeline.
__global__ void __launch_bounds__(256) k3_kernel(
    const float* __restrict__ A, const float* __restrict__ B,
    const float* __restrict__ bias) {
    constexpr int SA = 64 * 20, SB = 16 * 136, SS = SA + SB;  // floats
    constexpr int NKT = CIN / 16;
    extern __shared__ float smem[];

    const int p0 = blockIdx.y * 128;
    const int n = blockIdx.z;
    const float* Bn = B + (size_t)n * CIN * HW;
    __half* Cn = d_f + (size_t)n * CMC * HW;

    const int tid = threadIdx.x;
    const int wid = tid >> 5, lane = tid & 31;
    const int wm = wid >> 2, wq = wid & 3;
    const int g = lane >> 2, tg = lane & 3;

    auto issue = [&](int s, int k0) {
        float* As_ = smem + s * SS;
        float* Bs_ = As_ + SA;
        {
            const int row = tid >> 2, kq = (tid & 3) << 2;
            cp16(&As_[row * 20 + kq], &A[(size_t)row * CIN + k0 + kq]);
        }
#pragma unroll
        for (int v = tid; v < 512; v += 256) {
            const int row = v >> 5, c4 = (v & 31) << 2;
            cp16(&Bs_[row * 136 + c4], &Bn[(size_t)(k0 + row) * HW + p0 + c4]);
        }
        cp_commit();
    };

    float acc[2][4][4];
#pragma unroll
    for (int i = 0; i < 2; i++)
#pragma unroll
        for (int j = 0; j < 4; j++)
#pragma unroll
            for (int q = 0; q < 4; q++) acc[i][j][q] = 0.f;

    issue(0, 0);
    issue(1, 16);

    for (int kt = 0; kt < NKT; kt++) {
        if (kt == NKT - 1)
            asm volatile("cp.async.wait_group 0;" ::: "memory");
        else
            asm volatile("cp.async.wait_group 1;" ::: "memory");
        __syncthreads();
        if (kt + 2 < NKT) issue((kt + 2) % 3, (kt + 2) * 16);

        const float* As_ = smem + (kt % 3) * SS;
        const float* Bs_ = As_ + SA;
#pragma unroll
        for (int ks = 0; ks < 16; ks += 8) {
            uint32_t af[2][4], bf[4][2];
#pragma unroll
            for (int i = 0; i < 2; i++) {
                const int m = wm * 32 + i * 16 + g;
                af[i][0] = __float_as_uint(f2tf32(As_[m * 20 + ks + tg]));
                af[i][1] = __float_as_uint(f2tf32(As_[(m + 8) * 20 + ks + tg]));
                af[i][2] = __float_as_uint(f2tf32(As_[m * 20 + ks + tg + 4]));
                af[i][3] = __float_as_uint(f2tf32(As_[(m + 8) * 20 + ks + tg + 4]));
            }
#pragma unroll
            for (int j = 0; j < 4; j++) {
                const int col = wq * 32 + j * 8 + g;
                bf[j][0] = __float_as_uint(f2tf32(Bs_[(ks + tg) * 136 + col]));
                bf[j][1] = __float_as_uint(f2tf32(Bs_[(ks + tg + 4) * 136 + col]));
            }
#pragma unroll
            for (int i = 0; i < 2; i++)
#pragma unroll
                for (int j = 0; j < 4; j++) mma_tf32(acc[i][j], af[i], bf[j]);
        }
    }
    // epilogue: relu + fp16 store
#pragma unroll
    for (int i = 0; i < 2; i++) {
        const int o = wm * 32 + i * 16 + g;
        const float bv0 = bias[o];
        const float bv1 = bias[o + 8];
#pragma unroll
        for (int j = 0; j < 4; j++) {
            const int px = p0 + wq * 32 + j * 8 + 2 * tg;
            *reinterpret_cast<__half2*>(&Cn[(size_t)o * HW + px]) =
                __floats2half2_rn(fmaxf(acc[i][j][0] + bv0, 0.f),
                                  fmaxf(acc[i][j][1] + bv0, 0.f));
            *reinterpret_cast<__half2*>(&Cn[(size_t)(o + 8) * HW + px]) =
                __floats2half2_rn(fmaxf(acc[i][j][2] + bv1, 0.f),
                                  fmaxf(acc[i][j][3] + bv1, 0.f));
        }
    }
}

// ---------------- K4b: out = Wcat @ ocat + cbias (fp16 HMMA m16n8k16) ----------------
// block 128o x 128px, 8 warps (2m x 4n), 3-stage cp.async, all-half tiles.
// A smem stride 24 halfs (conflict-free: bank = (12m+tg) mod 32 is a permutation).
__global__ void __launch_bounds__(256) k4b_kernel(
    const __half* __restrict__ A, const float* __restrict__ bias,
    float* __restrict__ C) {
    constexpr int SA_B = 128 * 24 * 2;            // A stage bytes (half)
    constexpr int SB_B = 16 * 136 * 2;            // B stage bytes (half)
    constexpr int SS_B = SA_B + SB_B;             // 10496 B
    constexpr int NKT = KCAT / 16;
    extern __shared__ char smemc[];

    const int o0 = blockIdx.x * 128;
    const int p0 = blockIdx.y * 128;
    const int n = blockIdx.z;
    const __half* Bn = d_ocat + (size_t)n * KCAT * HW;
    float* Cn = C + (size_t)n * MTOT * HW;

    const int tid = threadIdx.x;
    const int wid = tid >> 5, lane = tid & 31;
    const int wm = wid >> 2, wq = wid & 3;
    const int g = lane >> 2, tg = lane & 3;

    auto issue = [&](int s, int k0) {
        __half* As_ = reinterpret_cast<__half*>(smemc + s * SS_B);
        __half* Bs_ = reinterpret_cast<__half*>(smemc + s * SS_B + SA_B);
        {
            const int row = tid >> 1, kq = (tid & 1) << 3;  // 128 rows x 2x8 halfs
            cp16(&As_[row * 24 + kq], &A[(size_t)(o0 + row) * KCAT + k0 + kq]);
        }
        {
            const int row = tid >> 4, pb = (tid & 15) << 3;  // 16 rows x 16x8 halfs
            cp16(&Bs_[row * 136 + pb], &Bn[(size_t)(k0 + row) * HW + p0 + pb]);
        }
        cp_commit();
    };

    float acc[4][4][4];
#pragma unroll
    for (int i = 0; i < 4; i++)
#pragma unroll
        for (int j = 0; j < 4; j++)
#pragma unroll
            for (int q = 0; q < 4; q++) acc[i][j][q] = 0.f;

    issue(0, 0);
    issue(1, 16);

    for (int kt = 0; kt < NKT; kt++) {
        if (kt == NKT - 1)
            asm volatile("cp.async.wait_group 0;" ::: "memory");
        else
            asm volatile("cp.async.wait_group 1;" ::: "memory");
        __syncthreads();
        if (kt + 2 < NKT) issue((kt + 2) % 3, (kt + 2) * 16);

        const __half* As_ = reinterpret_cast<const __half*>(smemc + (kt % 3) * SS_B);
        const __half* Bs_ = reinterpret_cast<const __half*>(smemc + (kt % 3) * SS_B + SA_B);

        uint32_t af[4][4], bf[4][2];
#pragma unroll
        for (int i = 0; i < 4; i++) {
            const int m = wm * 64 + i * 16 + g;
            af[i][0] = *reinterpret_cast<const uint32_t*>(&As_[m * 24 + 2 * tg]);
            af[i][1] = *reinterpret_cast<const uint32_t*>(&As_[(m + 8) * 24 + 2 * tg]);
            af[i][2] = *reinterpret_cast<const uint32_t*>(&As_[m * 24 + 2 * tg + 8]);
            af[i][3] = *reinterpret_cast<const uint32_t*>(&As_[(m + 8) * 24 + 2 * tg + 8]);
        }
#pragma unroll
        for (int j = 0; j < 4; j++) {
            const int col = wq * 32 + j * 8 + g;
            // B fragment (col-major n8k16): {B[2tg][col],B[2tg+1][col]}, {B[2tg+8][col],B[2tg+9][col]}
            uint32_t l0 = (uint32_t)__half_as_ushort(Bs_[(2 * tg) * 136 + col]);
            uint32_t h0 = (uint32_t)__half_as_ushort(Bs_[(2 * tg + 1) * 136 + col]);
            uint32_t l1 = (uint32_t)__half_as_ushort(Bs_[(2 * tg + 8) * 136 + col]);
            uint32_t h1 = (uint32_t)__half_as_ushort(Bs_[(2 * tg + 9) * 136 + col]);
            bf[j][0] = l0 | (h0 << 16);
            bf[j][1] = l1 | (h1 << 16);
        }
#pragma unroll
        for (int i = 0; i < 4; i++)
#pragma unroll
            for (int j = 0; j < 4; j++) mma_f16(acc[i][j], af[i], bf[j]);
    }
    // epilogue
#pragma unroll
    for (int i = 0; i < 4; i++) {
        const int o = o0 + wm * 64 + i * 16 + g;
        const float bv0 = bias[o];
        const float bv1 = bias[o + 8];
#pragma unroll
        for (int j = 0; j < 4; j++) {
            const int px = p0 + wq * 32 + j * 8 + 2 * tg;
            *reinterpret_cast<float2*>(&Cn[(size_t)o * HW + px]) =
                make_float2(acc[i][j][0] + bv0, acc[i][j][1] + bv0);
            *reinterpret_cast<float2*>(&Cn[(size_t)(o + 8) * HW + px]) =
                make_float2(acc[i][j][2] + bv1, acc[i][j][3] + bv1);
        }
    }
}

// ---------------- K4a: depthwise convs, fp16 in/out, 4 px/thread ----------------
__global__ void __launch_bounds__(256) dw_kernel() {
    const int c = blockIdx.x;  // 64
    const int n = blockIdx.y;  // 32
    __shared__ float sm[72 * 72];
    __shared__ float kk[43];
    const int tid = threadIdx.x;
    for (int i = tid; i < 72 * 72; i += 256) sm[i] = 0.f;
    __syncthreads();
    const __half2* fb2 = reinterpret_cast<const __half2*>(
        d_f + ((size_t)n * CMC + c) * HW);
    for (int i = tid; i < HW / 2; i += 256) {
        const float2 v = __half22float2(fb2[i]);
        const int idx = i * 2;
        const int base = ((idx >> 6) + 4) * 72 + (idx & 63) + 4;
        sm[base] = v.x;
        sm[base + 1] = v.y;
    }
    if (tid < 43) kk[tid] = d_ker[((size_t)n * CMC + c) * 43 + tid];
    __syncthreads();

    __half* o1 = d_ocat + ((size_t)n * KCAT + c) * HW;
    __half* o2 = o1 + (size_t)64 * HW;
    __half* o3 = o1 + (size_t)128 * HW;

    const int w0 = (tid & 15) * 4;

#pragma unroll
    for (int pass = 0; pass < 4; pass++) {
        const int h = pass * 16 + (tid >> 4);
        float s1[4] = {0.f, 0.f, 0.f, 0.f};
        float s2[4] = {0.f, 0.f, 0.f, 0.f};
        float s3[4] = {0.f, 0.f, 0.f, 0.f};
        float rv[12];

        auto loadrow = [&](int ri) {
            const float4 a = *reinterpret_cast<const float4*>(&sm[ri * 72 + w0]);
            const float4 b = *reinterpret_cast<const float4*>(&sm[ri * 72 + w0 + 4]);
            const float4 d = *reinterpret_cast<const float4*>(&sm[ri * 72 + w0 + 8]);
            rv[0] = a.x; rv[1] = a.y; rv[2] = a.z; rv[3] = a.w;
            rv[4] = b.x; rv[5] = b.y; rv[6] = b.z; rv[7] = b.w;
            rv[8] = d.x; rv[9] = d.y; rv[10] = d.z; rv[11] = d.w;
        };
        auto b1row = [&](int dy) {
#pragma unroll
            for (int dx = 0; dx < 5; dx++) {
                const float kv = kk[dy * 5 + dx];
#pragma unroll
                for (int px = 0; px < 4; px++) s1[px] = fmaf(kv, rv[px + dx + 2], s1[px]);
            }
        };
        auto b2row = [&](int dy2) {
#pragma unroll
            for (int dx = 0; dx < 3; dx++) {
                const float kv = kk[25 + dy2 * 3 + dx];
#pragma unroll
                for (int px = 0; px < 4; px++) s2[px] = fmaf(kv, rv[px + 2 * dx + 2], s2[px]);
            }
        };
        auto b3row = [&](int dy4) {
#pragma unroll
            for (int dx = 0; dx < 3; dx++) {
                const float kv = kk[34 + dy4 * 3 + dx];
#pragma unroll
                for (int px = 0; px < 4; px++) s3[px] = fmaf(kv, rv[px + 4 * dx], s3[px]);
            }
        };

        loadrow(h);     b3row(0);
        loadrow(h + 2); b1row(0); b2row(0);
        loadrow(h + 3); b1row(1);
        loadrow(h + 4); b1row(2); b2row(1); b3row(1);
        loadrow(h + 5); b1row(3);
        loadrow(h + 6); b1row(4); b2row(2);
        loadrow(h + 8); b3row(2);

        const int i2 = (h * 64 + w0) >> 1;
        reinterpret_cast<__half2*>(o1)[i2]     = __floats2half2_rn(s1[0], s1[1]);
        reinterpret_cast<__half2*>(o1)[i2 + 1] = __floats2half2_rn(s1[2], s1[3]);
        reinterpret_cast<__half2*>(o2)[i2]     = __floats2half2_rn(s2[0], s2[1]);
        reinterpret_cast<__half2*>(o2)[i2 + 1] = __floats2half2_rn(s2[2], s2[3]);
        reinterpret_cast<__half2*>(o3)[i2]     = __floats2half2_rn(s3[0], s3[1]);
        reinterpret_cast<__half2*>(o3)[i2 + 1] = __floats2half2_rn(s3[2], s3[3]);
    }
}

// ---------------- host launch ----------------
extern "C" void kernel_launch(void* const* d_in, const int* in_sizes, int n_in,
                              void* d_out, int out_size) {
    (void)in_sizes; (void)n_in; (void)out_size;
    const float* x      = (const float*)d_in[0];
    const float* conv_w = (const float*)d_in[1];
    const float* conv_b = (const float*)d_in[2];
    const float* ckw    = (const float*)d_in[3];
    const float* ckb    = (const float*)d_in[4];
    const float* ck2w   = (const float*)d_in[5];
    const float* ck2b   = (const float*)d_in[6];
    const float* ckd4w  = (const float*)d_in[7];
    const float* ckd4b  = (const float*)d_in[8];
    const float* kw     = (const float*)d_in[9];
    const float* kb     = (const float*)d_in[10];
    const float* k2w    = (const float*)d_in[11];
    const float* k2b    = (const float*)d_in[12];
    const float* kd4w   = (const float*)d_in[13];
    const float* kd4b   = (const float*)d_in[14];
    const float* fuse_w = (const float*)d_in[15];
    const float* fuse_b = (const float*)d_in[16];
    const float* fc_w   = (const float*)d_in[17];
    const float* fc_b   = (const float*)d_in[18];
    float* out = (float*)d_out;

    void *p_Wcat = nullptr, *p_cbias = nullptr;
    cudaGetSymbolAddress(&p_Wcat, d_Wcat);
    cudaGetSymbolAddress(&p_cbias, d_cbias);

    constexpr int SMEM_K3  = 3 * (64 * 20 + 16 * 136) * 4;                // 41472 B
    constexpr int SMEM_K4B = 3 * (128 * 24 * 2 + 16 * 136 * 2);           // 31488 B
    cudaFuncSetAttribute(k3_kernel, cudaFuncAttributeMaxDynamicSharedMemorySize, SMEM_K3);
    cudaFuncSetAttribute(k4b_kernel, cudaFuncAttributeMaxDynamicSharedMemorySize, SMEM_K4B);

    // K1: spatial means
    mean_kernel<<<NB * CIN, 256>>>(x);
    // K2a: g + dynamic depthwise kernels (warp-parallel reduction)
    gker_kernel<<<256, 256>>>(conv_w, conv_b, ckw, ckb, ck2w, ck2b, ckd4w, ckd4b,
                              kw, kb, k2w, k2b, kd4w, kd4b);
    // K2b: collapsed fuse+fc weights (fp16)
    wcat_kernel<<<(MTOT * KCAT + MTOT + 255) / 256, 256>>>(fc_w, fc_b, fuse_w, fuse_b);
    // K3: f = relu(1x1 conv 256->64), tf32 mma, fp16 out
    k3_kernel<<<dim3(1, HW / 128, NB), 256, SMEM_K3>>>(conv_w, x, conv_b);
    // K4a: dynamic depthwise (3 branches) -> ocat (fp16)
    dw_kernel<<<dim3(CMC, NB), 256>>>();
    // K4b: out = Wcat @ ocat + cbias (fp16 HMMA m16n8k16)
    k4b_kernel<<<dim3(MTOT / 128, HW / 128, NB), 256, SMEM_K4B>>>(
        (const __half*)p_Wcat, (const float*)p_cbias, out);
}

// round 13
// speedup vs baseline: 2.2136x; 1.1153x over previous
#include <cuda_runtime.h>
#include <cuda_fp16.h>
#include <cstdint>
#include <cstddef>

#define HW   4096
#define NB   32
#define CIN  256
#define CMC  64
#define MTOT 384
#define KCAT 192

// ---------------- scratch (static device globals; no allocation) ----------------
__device__ float  d_mean[NB * CIN];
__device__ float  d_ker[NB * CMC * 43];
__device__ __half d_Wcat[MTOT * KCAT];                    // fp16 (10-bit mantissa = tf32)
__device__ float  d_cbias[MTOT];
__device__ __half d_f[(size_t)NB * CMC * HW];             // 16.8 MB (fp16)
__device__ __half d_ocat[(size_t)NB * KCAT * HW];         // 50.3 MB (fp16)

// ---------------- helpers ----------------
__device__ __forceinline__ float f2tf32(float f) {
    uint32_t r;
    asm("cvt.rna.tf32.f32 %0, %1;" : "=r"(r) : "f"(f));
    return __uint_as_float(r);
}
__device__ __forceinline__ void mma_tf32(float c[4], const uint32_t a[4],
                                         const uint32_t b[2]) {
    asm volatile(
        "mma.sync.aligned.m16n8k8.row.col.f32.tf32.tf32.f32 "
        "{%0,%1,%2,%3}, {%4,%5,%6,%7}, {%8,%9}, {%0,%1,%2,%3};"
        : "+f"(c[0]), "+f"(c[1]), "+f"(c[2]), "+f"(c[3])
        : "r"(a[0]), "r"(a[1]), "r"(a[2]), "r"(a[3]), "r"(b[0]), "r"(b[1]));
}
__device__ __forceinline__ void mma_f16(float c[4], const uint32_t a[4],
                                        const uint32_t b[2]) {
    asm volatile(
        "mma.sync.aligned.m16n8k16.row.col.f32.f16.f16.f32 "
        "{%0,%1,%2,%3}, {%4,%5,%6,%7}, {%8,%9}, {%0,%1,%2,%3};"
        : "+f"(c[0]), "+f"(c[1]), "+f"(c[2]), "+f"(c[3])
        : "r"(a[0]), "r"(a[1]), "r"(a[2]), "r"(a[3]), "r"(b[0]), "r"(b[1]));
}
__device__ __forceinline__ void cp16(void* sptr, const void* g) {
    unsigned sa = (unsigned)__cvta_generic_to_shared(sptr);
    asm volatile("cp.async.cg.shared.global [%0], [%1], 16;" :: "r"(sa), "l"(g));
}
__device__ __forceinline__ void cp_commit() {
    asm volatile("cp.async.commit_group;" ::: "memory");
}
__device__ __forceinline__ void ldsm_x4(uint32_t& r0, uint32_t& r1, uint32_t& r2,
                                        uint32_t& r3, uint32_t addr) {
    asm volatile("ldmatrix.sync.aligned.m8n8.x4.shared.b16 {%0,%1,%2,%3}, [%4];"
                 : "=r"(r0), "=r"(r1), "=r"(r2), "=r"(r3) : "r"(addr));
}
__device__ __forceinline__ void ldsm_x4_t(uint32_t& r0, uint32_t& r1, uint32_t& r2,
                                          uint32_t& r3, uint32_t addr) {
    asm volatile("ldmatrix.sync.aligned.m8n8.x4.trans.shared.b16 {%0,%1,%2,%3}, [%4];"
                 : "=r"(r0), "=r"(r1), "=r"(r2), "=r"(r3) : "r"(addr));
}

// ---------------- K1: per-(n,c) spatial mean ----------------
__global__ void __launch_bounds__(256) mean_kernel(const float* __restrict__ x) {
    const int idx = blockIdx.x;
    const float4* p = reinterpret_cast<const float4*>(x + (size_t)idx * HW);
    float s = 0.f;
#pragma unroll
    for (int i = 0; i < 4; i++) {
        float4 v = p[threadIdx.x + i * 256];
        s += (v.x + v.y) + (v.z + v.w);
    }
#pragma unroll
    for (int o = 16; o; o >>= 1) s += __shfl_down_sync(0xffffffffu, s, o);
    __shared__ float ws[8];
    if ((threadIdx.x & 31) == 0) ws[threadIdx.x >> 5] = s;
    __syncthreads();
    if (threadIdx.x < 8) {
        float t = ws[threadIdx.x];
#pragma unroll
        for (int o = 4; o; o >>= 1) t += __shfl_down_sync(0xffu, t, o);
        if (threadIdx.x == 0) d_mean[idx] = t * (1.f / 4096.f);
    }
}

// ---------------- K2a: g + dynamic kernels (warp per (n,c)) ----------------
__global__ void __launch_bounds__(256) gker_kernel(
    const float* __restrict__ conv_w, const float* __restrict__ conv_b,
    const float* __restrict__ ckw, const float* __restrict__ ckb,
    const float* __restrict__ ck2w, const float* __restrict__ ck2b,
    const float* __restrict__ ckd4w, const float* __restrict__ ckd4b,
    const float* __restrict__ kw, const float* __restrict__ kb,
    const float* __restrict__ k2w, const float* __restrict__ k2b,
    const float* __restrict__ kd4w, const float* __restrict__ kd4b) {
    const int t = blockIdx.x * 8 + (threadIdx.x >> 5);  // (n, c), 2048 warps
    const int lane = threadIdx.x & 31;
    const int n = t >> 6, c = t & 63;
    const float* mrow = &d_mean[n * CIN];
    const float* wrow = &conv_w[c * CIN];
    float s = 0.f;
#pragma unroll
    for (int i = 0; i < 8; i++) {
        const int k = lane + 32 * i;
        s = fmaf(mrow[k], wrow[k], s);
    }
#pragma unroll
    for (int o = 16; o; o >>= 1) s += __shfl_xor_sync(0xffffffffu, s, o);
    const float g = fmaxf(s + conv_b[c], 0.f);
    float* kp = &d_ker[(size_t)t * 43];
    if (lane < 25) kp[lane] = fmaf(*ckw, fmaf(g, kw[lane], kb[lane]), *ckb);
    if (lane < 9) {
        kp[25 + lane] = fmaf(*ck2w, fmaf(g, k2w[lane], k2b[lane]), *ck2b);
        kp[34 + lane] = fmaf(*ckd4w, fmaf(g, kd4w[lane], kd4b[lane]), *ckd4b);
    }
}

// ---------------- K2b: collapsed weights Wcat (fp16) and cbias ----------------
__global__ void __launch_bounds__(256) wcat_kernel(
    const float* __restrict__ fc_w, const float* __restrict__ fc_b,
    const float* __restrict__ fuse_w, const float* __restrict__ fuse_b) {
    const int m = blockIdx.x * 256 + threadIdx.x;
    if (m < MTOT * KCAT) {
        const int o = m / KCAT, cs = m % KCAT;
        const int b = cs >> 6, c = cs & 63;
        const float* fcr = &fc_w[o * 384 + b * 128];
        float s = 0.f;
#pragma unroll 4
        for (int j = 0; j < 128; j++) s = fmaf(fcr[j], fuse_w[j * 64 + c], s);
        d_Wcat[m] = __float2half_rn(s);
    } else {
        const int o = m - MTOT * KCAT;
        if (o < MTOT) {
            float s = fc_b[o];
            for (int j = 0; j < 384; j++)
                s = fmaf(fc_w[o * 384 + j], fuse_b[j & 127], s);
            d_cbias[o] = s;
        }
    }
}

// ---------------- K3: f = relu(conv_w @ x + b), tf32 mma, 4-stage pipeline ----------------
__global__ void __launch_bounds__(256) k3_kernel(
    const float* __restrict__ A, const float* __restrict__ B,
    const float* __restrict__ bias) {
    constexpr int SA = 64 * 20, SB = 16 * 136, SS = SA + SB;  // floats
    constexpr int NKT = CIN / 16;
    extern __shared__ float smem[];

    const int p0 = blockIdx.y * 128;
    const int n = blockIdx.z;
    const float* Bn = B + (size_t)n * CIN * HW;
    __half* Cn = d_f + (size_t)n * CMC * HW;

    const int tid = threadIdx.x;
    const int wid = tid >> 5, lane = tid & 31;
    const int wm = wid >> 2, wq = wid & 3;
    const int g = lane >> 2, tg = lane & 3;

    auto issue = [&](int s, int k0) {
        float* As_ = smem + s * SS;
        float* Bs_ = As_ + SA;
        {
            const int row = tid >> 2, kq = (tid & 3) << 2;
            cp16(&As_[row * 20 + kq], &A[(size_t)row * CIN + k0 + kq]);
        }
#pragma unroll
        for (int v = tid; v < 512; v += 256) {
            const int row = v >> 5, c4 = (v & 31) << 2;
            cp16(&Bs_[row * 136 + c4], &Bn[(size_t)(k0 + row) * HW + p0 + c4]);
        }
        cp_commit();
    };

    float acc[2][4][4];
#pragma unroll
    for (int i = 0; i < 2; i++)
#pragma unroll
        for (int j = 0; j < 4; j++)
#pragma unroll
            for (int q = 0; q < 4; q++) acc[i][j][q] = 0.f;

    issue(0, 0);
    issue(1, 16);
    issue(2, 32);

    for (int kt = 0; kt < NKT; kt++) {
        if (kt + 3 <= NKT)
            asm volatile("cp.async.wait_group 2;" ::: "memory");
        else if (kt + 2 == NKT)
            asm volatile("cp.async.wait_group 1;" ::: "memory");
        else
            asm volatile("cp.async.wait_group 0;" ::: "memory");
        __syncthreads();
        if (kt + 3 < NKT) issue((kt + 3) & 3, (kt + 3) * 16);

        const float* As_ = smem + (kt & 3) * SS;
        const float* Bs_ = As_ + SA;
#pragma unroll
        for (int ks = 0; ks < 16; ks += 8) {
            uint32_t af[2][4], bf[4][2];
#pragma unroll
            for (int i = 0; i < 2; i++) {
                const int m = wm * 32 + i * 16 + g;
                af[i][0] = __float_as_uint(f2tf32(As_[m * 20 + ks + tg]));
                af[i][1] = __float_as_uint(f2tf32(As_[(m + 8) * 20 + ks + tg]));
                af[i][2] = __float_as_uint(f2tf32(As_[m * 20 + ks + tg + 4]));
                af[i][3] = __float_as_uint(f2tf32(As_[(m + 8) * 20 + ks + tg + 4]));
            }
#pragma unroll
            for (int j = 0; j < 4; j++) {
                const int col = wq * 32 + j * 8 + g;
                bf[j][0] = __float_as_uint(f2tf32(Bs_[(ks + tg) * 136 + col]));
                bf[j][1] = __float_as_uint(f2tf32(Bs_[(ks + tg + 4) * 136 + col]));
            }
#pragma unroll
            for (int i = 0; i < 2; i++)
#pragma unroll
                for (int j = 0; j < 4; j++) mma_tf32(acc[i][j], af[i], bf[j]);
        }
    }
    // epilogue: relu + fp16 store
#pragma unroll
    for (int i = 0; i < 2; i++) {
        const int o = wm * 32 + i * 16 + g;
        const float bv0 = bias[o];
        const float bv1 = bias[o + 8];
#pragma unroll
        for (int j = 0; j < 4; j++) {
            const int px = p0 + wq * 32 + j * 8 + 2 * tg;
            *reinterpret_cast<__half2*>(&Cn[(size_t)o * HW + px]) =
                __floats2half2_rn(fmaxf(acc[i][j][0] + bv0, 0.f),
                                  fmaxf(acc[i][j][1] + bv0, 0.f));
            *reinterpret_cast<__half2*>(&Cn[(size_t)(o + 8) * HW + px]) =
                __floats2half2_rn(fmaxf(acc[i][j][2] + bv1, 0.f),
                                  fmaxf(acc[i][j][3] + bv1, 0.f));
        }
    }
}

// ---------------- K4b: out = Wcat @ ocat + cbias (fp16 HMMA + ldmatrix) ----------------
// block 128o x 128px, 8 warps (2m x 4n), 4-stage cp.async, all-half tiles.
// A stride 24 halfs, B stride 136 halfs — both ldmatrix conflict-free.
__global__ void __launch_bounds__(256) k4b_kernel(
    const __half* __restrict__ A, const float* __restrict__ bias,
    float* __restrict__ C) {
    constexpr int SA_B = 128 * 24 * 2;            // A stage bytes (half)
    constexpr int SB_B = 16 * 136 * 2;            // B stage bytes (half)
    constexpr int SS_B = SA_B + SB_B;             // 10496 B
    constexpr int NKT = KCAT / 16;
    extern __shared__ char smemc[];

    const int o0 = blockIdx.x * 128;
    const int p0 = blockIdx.y * 128;
    const int n = blockIdx.z;
    const __half* Bn = d_ocat + (size_t)n * KCAT * HW;
    float* Cn = C + (size_t)n * MTOT * HW;

    const int tid = threadIdx.x;
    const int wid = tid >> 5, lane = tid & 31;
    const int wm = wid >> 2, wq = wid & 3;
    const int g = lane >> 2, tg = lane & 3;

    // per-lane ldmatrix address offsets (in halfs, relative to stage base)
    const int rin = lane & 7, sel = lane >> 3;          // matrix row / matrix select
    // A .x4: matrices (m,k0),(m+8,k0),(m,k8),(m+8,k8); per-i base adds i*16*24
    const int a_off = (((sel & 1) << 3) + rin) * 24 + ((sel >> 1) << 3);
    // B .x4.trans: matrices (k0,n0),(k8,n0),(k0,n8),(k8,n8); per-jj base adds jj*16
    const int b_off = (((sel & 1) << 3) + rin) * 136 + wq * 32 + ((sel >> 1) << 3);

    auto issue = [&](int s, int k0) {
        __half* As_ = reinterpret_cast<__half*>(smemc + s * SS_B);
        __half* Bs_ = reinterpret_cast<__half*>(smemc + s * SS_B + SA_B);
        {
            const int row = tid >> 1, kq = (tid & 1) << 3;
            cp16(&As_[row * 24 + kq], &A[(size_t)(o0 + row) * KCAT + k0 + kq]);
        }
        {
            const int row = tid >> 4, pb = (tid & 15) << 3;
            cp16(&Bs_[row * 136 + pb], &Bn[(size_t)(k0 + row) * HW + p0 + pb]);
        }
        cp_commit();
    };

    float acc[4][4][4];
#pragma unroll
    for (int i = 0; i < 4; i++)
#pragma unroll
        for (int j = 0; j < 4; j++)
#pragma unroll
            for (int q = 0; q < 4; q++) acc[i][j][q] = 0.f;

    issue(0, 0);
    issue(1, 16);
    issue(2, 32);

    for (int kt = 0; kt < NKT; kt++) {
        if (kt + 3 <= NKT)
            asm volatile("cp.async.wait_group 2;" ::: "memory");
        else if (kt + 2 == NKT)
            asm volatile("cp.async.wait_group 1;" ::: "memory");
        else
            asm volatile("cp.async.wait_group 0;" ::: "memory");
        __syncthreads();
        if (kt + 3 < NKT) issue((kt + 3) & 3, (kt + 3) * 16);

        const __half* As_ = reinterpret_cast<const __half*>(smemc + (kt & 3) * SS_B);
        const __half* Bs_ = reinterpret_cast<const __half*>(smemc + (kt & 3) * SS_B + SA_B);
        const uint32_t a_base = (uint32_t)__cvta_generic_to_shared(As_);
        const uint32_t b_base = (uint32_t)__cvta_generic_to_shared(Bs_);

        uint32_t af[4][4], bf[4][2];
#pragma unroll
        for (int i = 0; i < 4; i++) {
            const uint32_t addr = a_base + (uint32_t)(((wm * 64 + i * 16) * 24 + a_off) * 2);
            ldsm_x4(af[i][0], af[i][1], af[i][2], af[i][3], addr);
        }
#pragma unroll
        for (int jj = 0; jj < 2; jj++) {
            const uint32_t addr = b_base + (uint32_t)((b_off + jj * 16) * 2);
            ldsm_x4_t(bf[2 * jj][0], bf[2 * jj][1], bf[2 * jj + 1][0], bf[2 * jj + 1][1],
                      addr);
        }
#pragma unroll
        for (int i = 0; i < 4; i++)
#pragma unroll
            for (int j = 0; j < 4; j++) mma_f16(acc[i][j], af[i], bf[j]);
    }
    // epilogue
#pragma unroll
    for (int i = 0; i < 4; i++) {
        const int o = o0 + wm * 64 + i * 16 + g;
        const float bv0 = bias[o];
        const float bv1 = bias[o + 8];
#pragma unroll
        for (int j = 0; j < 4; j++) {
            const int px = p0 + wq * 32 + j * 8 + 2 * tg;
            *reinterpret_cast<float2*>(&Cn[(size_t)o * HW + px]) =
                make_float2(acc[i][j][0] + bv0, acc[i][j][1] + bv0);
            *reinterpret_cast<float2*>(&Cn[(size_t)(o + 8) * HW + px]) =
                make_float2(acc[i][j][2] + bv1, acc[i][j][3] + bv1);
        }
    }
}

// ---------------- K4a: depthwise convs, fp16 in/out, 4 px/thread ----------------
__global__ void __launch_bounds__(256) dw_kernel() {
    const int c = blockIdx.x;  // 64
    const int n = blockIdx.y;  // 32
    __shared__ float sm[72 * 72];
    __shared__ float kk[43];
    const int tid = threadIdx.x;
    for (int i = tid; i < 72 * 72; i += 256) sm[i] = 0.f;
    __syncthreads();
    const __half2* fb2 = reinterpret_cast<const __half2*>(
        d_f + ((size_t)n * CMC + c) * HW);
    for (int i = tid; i < HW / 2; i += 256) {
        const float2 v = __half22float2(fb2[i]);
        const int idx = i * 2;
        const int base = ((idx >> 6) + 4) * 72 + (idx & 63) + 4;
        sm[base] = v.x;
        sm[base + 1] = v.y;
    }
    if (tid < 43) kk[tid] = d_ker[((size_t)n * CMC + c) * 43 + tid];
    __syncthreads();

    __half* o1 = d_ocat + ((size_t)n * KCAT + c) * HW;
    __half* o2 = o1 + (size_t)64 * HW;
    __half* o3 = o1 + (size_t)128 * HW;

    const int w0 = (tid & 15) * 4;

#pragma unroll
    for (int pass = 0; pass < 4; pass++) {
        const int h = pass * 16 + (tid >> 4);
        float s1[4] = {0.f, 0.f, 0.f, 0.f};
        float s2[4] = {0.f, 0.f, 0.f, 0.f};
        float s3[4] = {0.f, 0.f, 0.f, 0.f};
        float rv[12];

        auto loadrow = [&](int ri) {
            const float4 a = *reinterpret_cast<const float4*>(&sm[ri * 72 + w0]);
            const float4 b = *reinterpret_cast<const float4*>(&sm[ri * 72 + w0 + 4]);
            const float4 d = *reinterpret_cast<const float4*>(&sm[ri * 72 + w0 + 8]);
            rv[0] = a.x; rv[1] = a.y; rv[2] = a.z; rv[3] = a.w;
            rv[4] = b.x; rv[5] = b.y; rv[6] = b.z; rv[7] = b.w;
            rv[8] = d.x; rv[9] = d.y; rv[10] = d.z; rv[11] = d.w;
        };
        auto b1row = [&](int dy) {
#pragma unroll
            for (int dx = 0; dx < 5; dx++) {
                const float kv = kk[dy * 5 + dx];
#pragma unroll
                for (int px = 0; px < 4; px++) s1[px] = fmaf(kv, rv[px + dx + 2], s1[px]);
            }
        };
        auto b2row = [&](int dy2) {
#pragma unroll
            for (int dx = 0; dx < 3; dx++) {
                const float kv = kk[25 + dy2 * 3 + dx];
#pragma unroll
                for (int px = 0; px < 4; px++) s2[px] = fmaf(kv, rv[px + 2 * dx + 2], s2[px]);
            }
        };
        auto b3row = [&](int dy4) {
#pragma unroll
            for (int dx = 0; dx < 3; dx++) {
                const float kv = kk[34 + dy4 * 3 + dx];
#pragma unroll
                for (int px = 0; px < 4; px++) s3[px] = fmaf(kv, rv[px + 4 * dx], s3[px]);
            }
        };

        loadrow(h);     b3row(0);
        loadrow(h + 2); b1row(0); b2row(0);
        loadrow(h + 3); b1row(1);
        loadrow(h + 4); b1row(2); b2row(1); b3row(1);
        loadrow(h + 5); b1row(3);
        loadrow(h + 6); b1row(4); b2row(2);
        loadrow(h + 8); b3row(2);

        const int i2 = (h * 64 + w0) >> 1;
        reinterpret_cast<__half2*>(o1)[i2]     = __floats2half2_rn(s1[0], s1[1]);
        reinterpret_cast<__half2*>(o1)[i2 + 1] = __floats2half2_rn(s1[2], s1[3]);
        reinterpret_cast<__half2*>(o2)[i2]     = __floats2half2_rn(s2[0], s2[1]);
        reinterpret_cast<__half2*>(o2)[i2 + 1] = __floats2half2_rn(s2[2], s2[3]);
        reinterpret_cast<__half2*>(o3)[i2]     = __floats2half2_rn(s3[0], s3[1]);
        reinterpret_cast<__half2*>(o3)[i2 + 1] = __floats2half2_rn(s3[2], s3[3]);
    }
}

// ---------------- host launch ----------------
extern "C" void kernel_launch(void* const* d_in, const int* in_sizes, int n_in,
                              void* d_out, int out_size) {
    (void)in_sizes; (void)n_in; (void)out_size;
    const float* x      = (const float*)d_in[0];
    const float* conv_w = (const float*)d_in[1];
    const float* conv_b = (const float*)d_in[2];
    const float* ckw    = (const float*)d_in[3];
    const float* ckb    = (const float*)d_in[4];
    const float* ck2w   = (const float*)d_in[5];
    const float* ck2b   = (const float*)d_in[6];
    const float* ckd4w  = (const float*)d_in[7];
    const float* ckd4b  = (const float*)d_in[8];
    const float* kw     = (const float*)d_in[9];
    const float* kb     = (const float*)d_in[10];
    const float* k2w    = (const float*)d_in[11];
    const float* k2b    = (const float*)d_in[12];
    const float* kd4w   = (const float*)d_in[13];
    const float* kd4b   = (const float*)d_in[14];
    const float* fuse_w = (const float*)d_in[15];
    const float* fuse_b = (const float*)d_in[16];
    const float* fc_w   = (const float*)d_in[17];
    const float* fc_b   = (const float*)d_in[18];
    float* out = (float*)d_out;

    void *p_Wcat = nullptr, *p_cbias = nullptr;
    cudaGetSymbolAddress(&p_Wcat, d_Wcat);
    cudaGetSymbolAddress(&p_cbias, d_cbias);

    constexpr int SMEM_K3  = 4 * (64 * 20 + 16 * 136) * 4;                // 55296 B
    constexpr int SMEM_K4B = 4 * (128 * 24 * 2 + 16 * 136 * 2);           // 41984 B
    cudaFuncSetAttribute(k3_kernel, cudaFuncAttributeMaxDynamicSharedMemorySize, SMEM_K3);
    cudaFuncSetAttribute(k4b_kernel, cudaFuncAttributeMaxDynamicSharedMemorySize, SMEM_K4B);

    // K1: spatial means
    mean_kernel<<<NB * CIN, 256>>>(x);
    // K2a: g + dynamic depthwise kernels (warp-parallel reduction)
    gker_kernel<<<256, 256>>>(conv_w, conv_b, ckw, ckb, ck2w, ck2b, ckd4w, ckd4b,
                              kw, kb, k2w, k2b, kd4w, kd4b);
    // K2b: collapsed fuse+fc weights (fp16)
    wcat_kernel<<<(MTOT * KCAT + MTOT + 255) / 256, 256>>>(fc_w, fc_b, fuse_w, fuse_b);
    // K3: f = relu(1x1 conv 256->64), tf32 mma, 4-stage pipeline
    k3_kernel<<<dim3(1, HW / 128, NB), 256, SMEM_K3>>>(conv_w, x, conv_b);
    // K4a: dynamic depthwise (3 branches) -> ocat (fp16)
    dw_kernel<<<dim3(CMC, NB), 256>>>();
    // K4b: out = Wcat @ ocat + cbias (fp16 HMMA m16n8k16 + ldmatrix)
    k4b_kernel<<<dim3(MTOT / 128, HW / 128, NB), 256, SMEM_K4B>>>(
        (const __half*)p_Wcat, (const float*)p_cbias, out);
}

// round 16
// speedup vs baseline: 2.5998x; 1.1745x over previous
#include <cuda_runtime.h>
#include <cuda_fp16.h>
#include <cstdint>
#include <cstddef>

#define HW   4096
#define NB   32
#define NBH  16
#define CIN  256
#define CMC  64
#define MTOT 384
#define KCAT 192

// ---------------- scratch (static device globals; no allocation) ----------------
__device__ float  d_mean[NB * CIN];
__device__ float  d_ker[NB * CMC * 43];
__device__ __half d_Wcat[MTOT * KCAT];                    // fp16 (10-bit mantissa = tf32)
__device__ float  d_cbias[MTOT];
__device__ __half d_f[(size_t)NB * CMC * HW];             // 16.8 MB (fp16)
__device__ __half d_ocat[(size_t)NB * KCAT * HW];         // 50.3 MB (fp16)

// ---------------- helpers ----------------
__device__ __forceinline__ float f2tf32(float f) {
    uint32_t r;
    asm("cvt.rna.tf32.f32 %0, %1;" : "=r"(r) : "f"(f));
    return __uint_as_float(r);
}
__device__ __forceinline__ void mma_tf32(float c[4], const uint32_t a[4],
                                         const uint32_t b[2]) {
    asm volatile(
        "mma.sync.aligned.m16n8k8.row.col.f32.tf32.tf32.f32 "
        "{%0,%1,%2,%3}, {%4,%5,%6,%7}, {%8,%9}, {%0,%1,%2,%3};"
        : "+f"(c[0]), "+f"(c[1]), "+f"(c[2]), "+f"(c[3])
        : "r"(a[0]), "r"(a[1]), "r"(a[2]), "r"(a[3]), "r"(b[0]), "r"(b[1]));
}
__device__ __forceinline__ void mma_f16(float c[4], const uint32_t a[4],
                                        const uint32_t b[2]) {
    asm volatile(
        "mma.sync.aligned.m16n8k16.row.col.f32.f16.f16.f32 "
        "{%0,%1,%2,%3}, {%4,%5,%6,%7}, {%8,%9}, {%0,%1,%2,%3};"
        : "+f"(c[0]), "+f"(c[1]), "+f"(c[2]), "+f"(c[3])
        : "r"(a[0]), "r"(a[1]), "r"(a[2]), "r"(a[3]), "r"(b[0]), "r"(b[1]));
}
__device__ __forceinline__ void cp16(void* sptr, const void* g) {
    unsigned sa = (unsigned)__cvta_generic_to_shared(sptr);
    asm volatile("cp.async.cg.shared.global [%0], [%1], 16;" :: "r"(sa), "l"(g));
}
__device__ __forceinline__ void cp_commit() {
    asm volatile("cp.async.commit_group;" ::: "memory");
}
__device__ __forceinline__ void ldsm_x4(uint32_t& r0, uint32_t& r1, uint32_t& r2,
                                        uint32_t& r3, uint32_t addr) {
    asm volatile("ldmatrix.sync.aligned.m8n8.x4.shared.b16 {%0,%1,%2,%3}, [%4];"
                 : "=r"(r0), "=r"(r1), "=r"(r2), "=r"(r3) : "r"(addr));
}
__device__ __forceinline__ void ldsm_x4_t(uint32_t& r0, uint32_t& r1, uint32_t& r2,
                                          uint32_t& r3, uint32_t addr) {
    asm volatile("ldmatrix.sync.aligned.m8n8.x4.trans.shared.b16 {%0,%1,%2,%3}, [%4];"
                 : "=r"(r0), "=r"(r1), "=r"(r2), "=r"(r3) : "r"(addr));
}

// ---------------- K1: per-(n,c) spatial mean (half batch per launch) ----------------
__global__ void __launch_bounds__(256) mean_kernel(const float* __restrict__ x, int n0) {
    const int idx = blockIdx.x + n0 * CIN;
    const float4* p = reinterpret_cast<const float4*>(x + (size_t)idx * HW);
    float s = 0.f;
#pragma unroll
    for (int i = 0; i < 4; i++) {
        float4 v = p[threadIdx.x + i * 256];
        s += (v.x + v.y) + (v.z + v.w);
    }
#pragma unroll
    for (int o = 16; o; o >>= 1) s += __shfl_down_sync(0xffffffffu, s, o);
    __shared__ float ws[8];
    if ((threadIdx.x & 31) == 0) ws[threadIdx.x >> 5] = s;
    __syncthreads();
    if (threadIdx.x < 8) {
        float t = ws[threadIdx.x];
#pragma unroll
        for (int o = 4; o; o >>= 1) t += __shfl_down_sync(0xffu, t, o);
        if (threadIdx.x == 0) d_mean[idx] = t * (1.f / 4096.f);
    }
}

// ---------------- K2a: g + dynamic kernels (warp per (n,c), half batch) ----------------
__global__ void __launch_bounds__(256) gker_kernel(
    const float* __restrict__ conv_w, const float* __restrict__ conv_b,
    const float* __restrict__ ckw, const float* __restrict__ ckb,
    const float* __restrict__ ck2w, const float* __restrict__ ck2b,
    const float* __restrict__ ckd4w, const float* __restrict__ ckd4b,
    const float* __restrict__ kw, const float* __restrict__ kb,
    const float* __restrict__ k2w, const float* __restrict__ k2b,
    const float* __restrict__ kd4w, const float* __restrict__ kd4b, int n0) {
    const int t = blockIdx.x * 8 + (threadIdx.x >> 5) + n0 * 64;  // (n, c)
    const int lane = threadIdx.x & 31;
    const int n = t >> 6, c = t & 63;
    const float* mrow = &d_mean[n * CIN];
    const float* wrow = &conv_w[c * CIN];
    float s = 0.f;
#pragma unroll
    for (int i = 0; i < 8; i++) {
        const int k = lane + 32 * i;
        s = fmaf(mrow[k], wrow[k], s);
    }
#pragma unroll
    for (int o = 16; o; o >>= 1) s += __shfl_xor_sync(0xffffffffu, s, o);
    const float g = fmaxf(s + conv_b[c], 0.f);
    float* kp = &d_ker[(size_t)t * 43];
    if (lane < 25) kp[lane] = fmaf(*ckw, fmaf(g, kw[lane], kb[lane]), *ckb);
    if (lane < 9) {
        kp[25 + lane] = fmaf(*ck2w, fmaf(g, k2w[lane], k2b[lane]), *ck2b);
        kp[34 + lane] = fmaf(*ckd4w, fmaf(g, kd4w[lane], kd4b[lane]), *ckd4b);
    }
}

// ---------------- K2b: collapsed weights Wcat (fp16) and cbias ----------------
__global__ void __launch_bounds__(256) wcat_kernel(
    const float* __restrict__ fc_w, const float* __restrict__ fc_b,
    const float* __restrict__ fuse_w, const float* __restrict__ fuse_b) {
    const int m = blockIdx.x * 256 + threadIdx.x;
    if (m < MTOT * KCAT) {
        const int o = m / KCAT, cs = m % KCAT;
        const int b = cs >> 6, c = cs & 63;
        const float* fcr = &fc_w[o * 384 + b * 128];
        float s = 0.f;
#pragma unroll 4
        for (int j = 0; j < 128; j++) s = fmaf(fcr[j], fuse_w[j * 64 + c], s);
        d_Wcat[m] = __float2half_rn(s);
    } else {
        const int o = m - MTOT * KCAT;
        if (o < MTOT) {
            float s = fc_b[o];
            for (int j = 0; j < 384; j++)
                s = fmaf(fc_w[o * 384 + j], fuse_b[j & 127], s);
            d_cbias[o] = s;
        }
    }
}

// ---------------- K3: f = relu(conv_w @ x + b), tf32 mma, 4-stage pipeline ----------------
__global__ void __launch_bounds__(256) k3_kernel(
    const float* __restrict__ A, const float* __restrict__ B,
    const float* __restrict__ bias, int n0) {
    constexpr int SA = 64 * 20, SB = 16 * 136, SS = SA + SB;  // floats
    constexpr int NKT = CIN / 16;
    extern __shared__ float smem[];

    const int p0 = blockIdx.y * 128;
    const int n = blockIdx.z + n0;
    const float* Bn = B + (size_t)n * CIN * HW;
    __half* Cn = d_f + (size_t)n * CMC * HW;

    const int tid = threadIdx.x;
    const int wid = tid >> 5, lane = tid & 31;
    const int wm = wid >> 2, wq = wid & 3;
    const int g = lane >> 2, tg = lane & 3;

    auto issue = [&](int s, int k0) {
        float* As_ = smem + s * SS;
        float* Bs_ = As_ + SA;
        {
            const int row = tid >> 2, kq = (tid & 3) << 2;
            cp16(&As_[row * 20 + kq], &A[(size_t)row * CIN + k0 + kq]);
        }
#pragma unroll
        for (int v = tid; v < 512; v += 256) {
            const int row = v >> 5, c4 = (v & 31) << 2;
            cp16(&Bs_[row * 136 + c4], &Bn[(size_t)(k0 + row) * HW + p0 + c4]);
        }
        cp_commit();
    };

    float acc[2][4][4];
#pragma unroll
    for (int i = 0; i < 2; i++)
#pragma unroll
        for (int j = 0; j < 4; j++)
#pragma unroll
            for (int q = 0; q < 4; q++) acc[i][j][q] = 0.f;

    issue(0, 0);
    issue(1, 16);
    issue(2, 32);

    for (int kt = 0; kt < NKT; kt++) {
        if (kt + 3 <= NKT)
            asm volatile("cp.async.wait_group 2;" ::: "memory");
        else if (kt + 2 == NKT)
            asm volatile("cp.async.wait_group 1;" ::: "memory");
        else
            asm volatile("cp.async.wait_group 0;" ::: "memory");
        __syncthreads();
        if (kt + 3 < NKT) issue((kt + 3) & 3, (kt + 3) * 16);

        const float* As_ = smem + (kt & 3) * SS;
        const float* Bs_ = As_ + SA;
#pragma unroll
        for (int ks = 0; ks < 16; ks += 8) {
            uint32_t af[2][4], bf[4][2];
#pragma unroll
            for (int i = 0; i < 2; i++) {
                const int m = wm * 32 + i * 16 + g;
                af[i][0] = __float_as_uint(f2tf32(As_[m * 20 + ks + tg]));
                af[i][1] = __float_as_uint(f2tf32(As_[(m + 8) * 20 + ks + tg]));
                af[i][2] = __float_as_uint(f2tf32(As_[m * 20 + ks + tg + 4]));
                af[i][3] = __float_as_uint(f2tf32(As_[(m + 8) * 20 + ks + tg + 4]));
            }
#pragma unroll
            for (int j = 0; j < 4; j++) {
                const int col = wq * 32 + j * 8 + g;
                bf[j][0] = __float_as_uint(f2tf32(Bs_[(ks + tg) * 136 + col]));
                bf[j][1] = __float_as_uint(f2tf32(Bs_[(ks + tg + 4) * 136 + col]));
            }
#pragma unroll
            for (int i = 0; i < 2; i++)
#pragma unroll
                for (int j = 0; j < 4; j++) mma_tf32(acc[i][j], af[i], bf[j]);
        }
    }
    // epilogue: relu + fp16 store
#pragma unroll
    for (int i = 0; i < 2; i++) {
        const int o = wm * 32 + i * 16 + g;
        const float bv0 = bias[o];
        const float bv1 = bias[o + 8];
#pragma unroll
        for (int j = 0; j < 4; j++) {
            const int px = p0 + wq * 32 + j * 8 + 2 * tg;
            *reinterpret_cast<__half2*>(&Cn[(size_t)o * HW + px]) =
                __floats2half2_rn(fmaxf(acc[i][j][0] + bv0, 0.f),
                                  fmaxf(acc[i][j][1] + bv0, 0.f));
            *reinterpret_cast<__half2*>(&Cn[(size_t)(o + 8) * HW + px]) =
                __floats2half2_rn(fmaxf(acc[i][j][2] + bv1, 0.f),
                                  fmaxf(acc[i][j][3] + bv1, 0.f));
        }
    }
}

// ---------------- K4b: out = Wcat @ ocat + cbias (fp16 HMMA + ldmatrix) ----------------
__global__ void __launch_bounds__(256) k4b_kernel(
    const __half* __restrict__ A, const float* __restrict__ bias,
    float* __restrict__ C, int n0) {
    constexpr int SA_B = 128 * 24 * 2;            // A stage bytes (half)
    constexpr int SB_B = 16 * 136 * 2;            // B stage bytes (half)
    constexpr int SS_B = SA_B + SB_B;             // 10496 B
    constexpr int NKT = KCAT / 16;
    extern __shared__ char smemc[];

    const int o0 = blockIdx.x * 128;
    const int p0 = blockIdx.y * 128;
    const int n = blockIdx.z + n0;
    const __half* Bn = d_ocat + (size_t)n * KCAT * HW;
    float* Cn = C + (size_t)n * MTOT * HW;

    const int tid = threadIdx.x;
    const int wid = tid >> 5, lane = tid & 31;
    const int wm = wid >> 2, wq = wid & 3;
    const int g = lane >> 2, tg = lane & 3;

    const int rin = lane & 7, sel = lane >> 3;
    const int a_off = (((sel & 1) << 3) + rin) * 24 + ((sel >> 1) << 3);
    const int b_off = (((sel & 1) << 3) + rin) * 136 + wq * 32 + ((sel >> 1) << 3);

    auto issue = [&](int s, int k0) {
        __half* As_ = reinterpret_cast<__half*>(smemc + s * SS_B);
        __half* Bs_ = reinterpret_cast<__half*>(smemc + s * SS_B + SA_B);
        {
            const int row = tid >> 1, kq = (tid & 1) << 3;
            cp16(&As_[row * 24 + kq], &A[(size_t)(o0 + row) * KCAT + k0 + kq]);
        }
        {
            const int row = tid >> 4, pb = (tid & 15) << 3;
            cp16(&Bs_[row * 136 + pb], &Bn[(size_t)(k0 + row) * HW + p0 + pb]);
        }
        cp_commit();
    };

    float acc[4][4][4];
#pragma unroll
    for (int i = 0; i < 4; i++)
#pragma unroll
        for (int j = 0; j < 4; j++)
#pragma unroll
            for (int q = 0; q < 4; q++) acc[i][j][q] = 0.f;

    issue(0, 0);
    issue(1, 16);
    issue(2, 32);

    for (int kt = 0; kt < NKT; kt++) {
        if (kt + 3 <= NKT)
            asm volatile("cp.async.wait_group 2;" ::: "memory");
        else if (kt + 2 == NKT)
            asm volatile("cp.async.wait_group 1;" ::: "memory");
        else
            asm volatile("cp.async.wait_group 0;" ::: "memory");
        __syncthreads();
        if (kt + 3 < NKT) issue((kt + 3) & 3, (kt + 3) * 16);

        const __half* As_ = reinterpret_cast<const __half*>(smemc + (kt & 3) * SS_B);
        const __half* Bs_ = reinterpret_cast<const __half*>(smemc + (kt & 3) * SS_B + SA_B);
        const uint32_t a_base = (uint32_t)__cvta_generic_to_shared(As_);
        const uint32_t b_base = (uint32_t)__cvta_generic_to_shared(Bs_);

        uint32_t af[4][4], bf[4][2];
#pragma unroll
        for (int i = 0; i < 4; i++) {
            const uint32_t addr = a_base + (uint32_t)(((wm * 64 + i * 16) * 24 + a_off) * 2);
            ldsm_x4(af[i][0], af[i][1], af[i][2], af[i][3], addr);
        }
#pragma unroll
        for (int jj = 0; jj < 2; jj++) {
            const uint32_t addr = b_base + (uint32_t)((b_off + jj * 16) * 2);
            ldsm_x4_t(bf[2 * jj][0], bf[2 * jj][1], bf[2 * jj + 1][0], bf[2 * jj + 1][1],
                      addr);
        }
#pragma unroll
        for (int i = 0; i < 4; i++)
#pragma unroll
            for (int j = 0; j < 4; j++) mma_f16(acc[i][j], af[i], bf[j]);
    }
    // epilogue
#pragma unroll
    for (int i = 0; i < 4; i++) {
        const int o = o0 + wm * 64 + i * 16 + g;
        const float bv0 = bias[o];
        const float bv1 = bias[o + 8];
#pragma unroll
        for (int j = 0; j < 4; j++) {
            const int px = p0 + wq * 32 + j * 8 + 2 * tg;
            *reinterpret_cast<float2*>(&Cn[(size_t)o * HW + px]) =
                make_float2(acc[i][j][0] + bv0, acc[i][j][1] + bv0);
            *reinterpret_cast<float2*>(&Cn[(size_t)(o + 8) * HW + px]) =
                make_float2(acc[i][j][2] + bv1, acc[i][j][3] + bv1);
        }
    }
}

// ---------------- K4a: depthwise convs, fp16 in/out, 4 px/thread ----------------
__global__ void __launch_bounds__(256) dw_kernel(int n0) {
    const int c = blockIdx.x;  // 64
    const int n = blockIdx.y + n0;
    __shared__ float sm[72 * 72];
    __shared__ float kk[43];
    const int tid = threadIdx.x;
    for (int i = tid; i < 72 * 72; i += 256) sm[i] = 0.f;
    __syncthreads();
    const __half2* fb2 = reinterpret_cast<const __half2*>(
        d_f + ((size_t)n * CMC + c) * HW);
    for (int i = tid; i < HW / 2; i += 256) {
        const float2 v = __half22float2(fb2[i]);
        const int idx = i * 2;
        const int base = ((idx >> 6) + 4) * 72 + (idx & 63) + 4;
        sm[base] = v.x;
        sm[base + 1] = v.y;
    }
    if (tid < 43) kk[tid] = d_ker[((size_t)n * CMC + c) * 43 + tid];
    __syncthreads();

    __half* o1 = d_ocat + ((size_t)n * KCAT + c) * HW;
    __half* o2 = o1 + (size_t)64 * HW;
    __half* o3 = o1 + (size_t)128 * HW;

    const int w0 = (tid & 15) * 4;

#pragma unroll
    for (int pass = 0; pass < 4; pass++) {
        const int h = pass * 16 + (tid >> 4);
        float s1[4] = {0.f, 0.f, 0.f, 0.f};
        float s2[4] = {0.f, 0.f, 0.f, 0.f};
        float s3[4] = {0.f, 0.f, 0.f, 0.f};
        float rv[12];

        auto loadrow = [&](int ri) {
            const float4 a = *reinterpret_cast<const float4*>(&sm[ri * 72 + w0]);
            const float4 b = *reinterpret_cast<const float4*>(&sm[ri * 72 + w0 + 4]);
            const float4 d = *reinterpret_cast<const float4*>(&sm[ri * 72 + w0 + 8]);
            rv[0] = a.x; rv[1] = a.y; rv[2] = a.z; rv[3] = a.w;
            rv[4] = b.x; rv[5] = b.y; rv[6] = b.z; rv[7] = b.w;
            rv[8] = d.x; rv[9] = d.y; rv[10] = d.z; rv[11] = d.w;
        };
        auto b1row = [&](int dy) {
#pragma unroll
            for (int dx = 0; dx < 5; dx++) {
                const float kv = kk[dy * 5 + dx];
#pragma unroll
                for (int px = 0; px < 4; px++) s1[px] = fmaf(kv, rv[px + dx + 2], s1[px]);
            }
        };
        auto b2row = [&](int dy2) {
#pragma unroll
            for (int dx = 0; dx < 3; dx++) {
                const float kv = kk[25 + dy2 * 3 + dx];
#pragma unroll
                for (int px = 0; px < 4; px++) s2[px] = fmaf(kv, rv[px + 2 * dx + 2], s2[px]);
            }
        };
        auto b3row = [&](int dy4) {
#pragma unroll
            for (int dx = 0; dx < 3; dx++) {
                const float kv = kk[34 + dy4 * 3 + dx];
#pragma unroll
                for (int px = 0; px < 4; px++) s3[px] = fmaf(kv, rv[px + 4 * dx], s3[px]);
            }
        };

        loadrow(h);     b3row(0);
        loadrow(h + 2); b1row(0); b2row(0);
        loadrow(h + 3); b1row(1);
        loadrow(h + 4); b1row(2); b2row(1); b3row(1);
        loadrow(h + 5); b1row(3);
        loadrow(h + 6); b1row(4); b2row(2);
        loadrow(h + 8); b3row(2);

        const int i2 = (h * 64 + w0) >> 1;
        reinterpret_cast<__half2*>(o1)[i2]     = __floats2half2_rn(s1[0], s1[1]);
        reinterpret_cast<__half2*>(o1)[i2 + 1] = __floats2half2_rn(s1[2], s1[3]);
        reinterpret_cast<__half2*>(o2)[i2]     = __floats2half2_rn(s2[0], s2[1]);
        reinterpret_cast<__half2*>(o2)[i2 + 1] = __floats2half2_rn(s2[2], s2[3]);
        reinterpret_cast<__half2*>(o3)[i2]     = __floats2half2_rn(s3[0], s3[1]);
        reinterpret_cast<__half2*>(o3)[i2 + 1] = __floats2half2_rn(s3[2], s3[3]);
    }
}

// ---------------- host launch: two batch-half pipelines on forked streams ----------------
extern "C" void kernel_launch(void* const* d_in, const int* in_sizes, int n_in,
                              void* d_out, int out_size) {
    (void)in_sizes; (void)n_in; (void)out_size;
    const float* x      = (const float*)d_in[0];
    const float* conv_w = (const float*)d_in[1];
    const float* conv_b = (const float*)d_in[2];
    const float* ckw    = (const float*)d_in[3];
    const float* ckb    = (const float*)d_in[4];
    const float* ck2w   = (const float*)d_in[5];
    const float* ck2b   = (const float*)d_in[6];
    const float* ckd4w  = (const float*)d_in[7];
    const float* ckd4b  = (const float*)d_in[8];
    const float* kw     = (const float*)d_in[9];
    const float* kb     = (const float*)d_in[10];
    const float* k2w    = (const float*)d_in[11];
    const float* k2b    = (const float*)d_in[12];
    const float* kd4w   = (const float*)d_in[13];
    const float* kd4b   = (const float*)d_in[14];
    const float* fuse_w = (const float*)d_in[15];
    const float* fuse_b = (const float*)d_in[16];
    const float* fc_w   = (const float*)d_in[17];
    const float* fc_b   = (const float*)d_in[18];
    float* out = (float*)d_out;

    void *p_Wcat = nullptr, *p_cbias = nullptr;
    cudaGetSymbolAddress(&p_Wcat, d_Wcat);
    cudaGetSymbolAddress(&p_cbias, d_cbias);

    constexpr int SMEM_K3  = 4 * (64 * 20 + 16 * 136) * 4;                // 55296 B
    constexpr int SMEM_K4B = 4 * (128 * 24 * 2 + 16 * 136 * 2);           // 41984 B

    // one-time resources (created on the uncaptured correctness call; reused under capture)
    static cudaStream_t sA = nullptr, sB = nullptr;
    static cudaEvent_t evRoot = nullptr, evW = nullptr, evA = nullptr, evB = nullptr;
    if (sA == nullptr) {
        cudaStreamCreateWithFlags(&sA, cudaStreamNonBlocking);
        cudaStreamCreateWithFlags(&sB, cudaStreamNonBlocking);
        cudaEventCreateWithFlags(&evRoot, cudaEventDisableTiming);
        cudaEventCreateWithFlags(&evW, cudaEventDisableTiming);
        cudaEventCreateWithFlags(&evA, cudaEventDisableTiming);
        cudaEventCreateWithFlags(&evB, cudaEventDisableTiming);
        cudaFuncSetAttribute(k3_kernel, cudaFuncAttributeMaxDynamicSharedMemorySize,
                             SMEM_K3);
        cudaFuncSetAttribute(k4b_kernel, cudaFuncAttributeMaxDynamicSharedMemorySize,
                             SMEM_K4B);
    }

    // fork from the (captured) default stream
    cudaEventRecord(evRoot, 0);
    cudaStreamWaitEvent(sA, evRoot, 0);
    cudaStreamWaitEvent(sB, evRoot, 0);

    // ---- stream A: shared wcat + batch half [0,16) ----
    wcat_kernel<<<(MTOT * KCAT + MTOT + 255) / 256, 256, 0, sA>>>(fc_w, fc_b, fuse_w,
                                                                  fuse_b);
    cudaEventRecord(evW, sA);
    mean_kernel<<<NBH * CIN, 256, 0, sA>>>(x, 0);
    gker_kernel<<<128, 256, 0, sA>>>(conv_w, conv_b, ckw, ckb, ck2w, ck2b, ckd4w, ckd4b,
                                     kw, kb, k2w, k2b, kd4w, kd4b, 0);
    k3_kernel<<<dim3(1, HW / 128, NBH), 256, SMEM_K3, sA>>>(conv_w, x, conv_b, 0);
    dw_kernel<<<dim3(CMC, NBH), 256, 0, sA>>>(0);
    k4b_kernel<<<dim3(MTOT / 128, HW / 128, NBH), 256, SMEM_K4B, sA>>>(
        (const __half*)p_Wcat, (const float*)p_cbias, out, 0);

    // ---- stream B: batch half [16,32) ----
    mean_kernel<<<NBH * CIN, 256, 0, sB>>>(x, NBH);
    gker_kernel<<<128, 256, 0, sB>>>(conv_w, conv_b, ckw, ckb, ck2w, ck2b, ckd4w, ckd4b,
                                     kw, kb, k2w, k2b, kd4w, kd4b, NBH);
    k3_kernel<<<dim3(1, HW / 128, NBH), 256, SMEM_K3, sB>>>(conv_w, x, conv_b, NBH);
    dw_kernel<<<dim3(CMC, NBH), 256, 0, sB>>>(NBH);
    cudaStreamWaitEvent(sB, evW, 0);  // k4b needs Wcat/cbias
    k4b_kernel<<<dim3(MTOT / 128, HW / 128, NBH), 256, SMEM_K4B, sB>>>(
        (const __half*)p_Wcat, (const float*)p_cbias, out, NBH);

    // join back to the default stream
    cudaEventRecord(evA, sA);
    cudaEventRecord(evB, sB);
    cudaStreamWaitEvent(0, evA, 0);
    cudaStreamWaitEvent(0, evB, 0);
}

// round 17
// speedup vs baseline: 2.6039x; 1.0015x over previous
#include <cuda_runtime.h>
#include <cuda_fp16.h>
#include <cstdint>
#include <cstddef>

#define HW   4096
#define NB   32
#define NBH  16
#define CIN  256
#define CMC  64
#define MTOT 384
#define KCAT 192

// ---------------- scratch (static device globals; no allocation) ----------------
__device__ float  d_mean[NB * CIN];
__device__ float  d_ker[NB * CMC * 43];
__device__ __half d_Wcat[MTOT * KCAT];                    // fp16 (10-bit mantissa = tf32)
__device__ float  d_cbias[MTOT];
__device__ __half d_f[(size_t)NB * CMC * HW];             // 16.8 MB (fp16)
__device__ __half d_ocat[(size_t)NB * KCAT * HW];         // 50.3 MB (fp16)

// ---------------- helpers ----------------
__device__ __forceinline__ float f2tf32(float f) {
    uint32_t r;
    asm("cvt.rna.tf32.f32 %0, %1;" : "=r"(r) : "f"(f));
    return __uint_as_float(r);
}
__device__ __forceinline__ void mma_tf32(float c[4], const uint32_t a[4],
                                         const uint32_t b[2]) {
    asm volatile(
        "mma.sync.aligned.m16n8k8.row.col.f32.tf32.tf32.f32 "
        "{%0,%1,%2,%3}, {%4,%5,%6,%7}, {%8,%9}, {%0,%1,%2,%3};"
        : "+f"(c[0]), "+f"(c[1]), "+f"(c[2]), "+f"(c[3])
        : "r"(a[0]), "r"(a[1]), "r"(a[2]), "r"(a[3]), "r"(b[0]), "r"(b[1]));
}
__device__ __forceinline__ void mma_f16(float c[4], const uint32_t a[4],
                                        const uint32_t b[2]) {
    asm volatile(
        "mma.sync.aligned.m16n8k16.row.col.f32.f16.f16.f32 "
        "{%0,%1,%2,%3}, {%4,%5,%6,%7}, {%8,%9}, {%0,%1,%2,%3};"
        : "+f"(c[0]), "+f"(c[1]), "+f"(c[2]), "+f"(c[3])
        : "r"(a[0]), "r"(a[1]), "r"(a[2]), "r"(a[3]), "r"(b[0]), "r"(b[1]));
}
__device__ __forceinline__ void cp16(void* sptr, const void* g) {
    unsigned sa = (unsigned)__cvta_generic_to_shared(sptr);
    asm volatile("cp.async.cg.shared.global [%0], [%1], 16;" :: "r"(sa), "l"(g));
}
__device__ __forceinline__ void cp_commit() {
    asm volatile("cp.async.commit_group;" ::: "memory");
}
__device__ __forceinline__ void ldsm_x4(uint32_t& r0, uint32_t& r1, uint32_t& r2,
                                        uint32_t& r3, uint32_t addr) {
    asm volatile("ldmatrix.sync.aligned.m8n8.x4.shared.b16 {%0,%1,%2,%3}, [%4];"
                 : "=r"(r0), "=r"(r1), "=r"(r2), "=r"(r3) : "r"(addr));
}
__device__ __forceinline__ void ldsm_x4_t(uint32_t& r0, uint32_t& r1, uint32_t& r2,
                                          uint32_t& r3, uint32_t addr) {
    asm volatile("ldmatrix.sync.aligned.m8n8.x4.trans.shared.b16 {%0,%1,%2,%3}, [%4];"
                 : "=r"(r0), "=r"(r1), "=r"(r2), "=r"(r3) : "r"(addr));
}

// ---------------- K1: per-(n,c) spatial mean (half batch per launch) ----------------
__global__ void __launch_bounds__(256) mean_kernel(const float* __restrict__ x, int n0) {
    const int idx = blockIdx.x + n0 * CIN;
    const float4* p = reinterpret_cast<const float4*>(x + (size_t)idx * HW);
    float s = 0.f;
#pragma unroll
    for (int i = 0; i < 4; i++) {
        float4 v = p[threadIdx.x + i * 256];
        s += (v.x + v.y) + (v.z + v.w);
    }
#pragma unroll
    for (int o = 16; o; o >>= 1) s += __shfl_down_sync(0xffffffffu, s, o);
    __shared__ float ws[8];
    if ((threadIdx.x & 31) == 0) ws[threadIdx.x >> 5] = s;
    __syncthreads();
    if (threadIdx.x < 8) {
        float t = ws[threadIdx.x];
#pragma unroll
        for (int o = 4; o; o >>= 1) t += __shfl_down_sync(0xffu, t, o);
        if (threadIdx.x == 0) d_mean[idx] = t * (1.f / 4096.f);
    }
}

// ---------------- K2a: g + dynamic kernels (warp per (n,c), half batch) ----------------
__global__ void __launch_bounds__(256) gker_kernel(
    const float* __restrict__ conv_w, const float* __restrict__ conv_b,
    const float* __restrict__ ckw, const float* __restrict__ ckb,
    const float* __restrict__ ck2w, const float* __restrict__ ck2b,
    const float* __restrict__ ckd4w, const float* __restrict__ ckd4b,
    const float* __restrict__ kw, const float* __restrict__ kb,
    const float* __restrict__ k2w, const float* __restrict__ k2b,
    const float* __restrict__ kd4w, const float* __restrict__ kd4b, int n0) {
    const int t = blockIdx.x * 8 + (threadIdx.x >> 5) + n0 * 64;  // (n, c)
    const int lane = threadIdx.x & 31;
    const int n = t >> 6, c = t & 63;
    const float* mrow = &d_mean[n * CIN];
    const float* wrow = &conv_w[c * CIN];
    float s = 0.f;
#pragma unroll
    for (int i = 0; i < 8; i++) {
        const int k = lane + 32 * i;
        s = fmaf(mrow[k], wrow[k], s);
    }
#pragma unroll
    for (int o = 16; o; o >>= 1) s += __shfl_xor_sync(0xffffffffu, s, o);
    const float g = fmaxf(s + conv_b[c], 0.f);
    float* kp = &d_ker[(size_t)t * 43];
    if (lane < 25) kp[lane] = fmaf(*ckw, fmaf(g, kw[lane], kb[lane]), *ckb);
    if (lane < 9) {
        kp[25 + lane] = fmaf(*ck2w, fmaf(g, k2w[lane], k2b[lane]), *ck2b);
        kp[34 + lane] = fmaf(*ckd4w, fmaf(g, kd4w[lane], kd4b[lane]), *ckd4b);
    }
}

// ---------------- K2b: collapsed weights Wcat (fp16) and cbias ----------------
__global__ void __launch_bounds__(256) wcat_kernel(
    const float* __restrict__ fc_w, const float* __restrict__ fc_b,
    const float* __restrict__ fuse_w, const float* __restrict__ fuse_b) {
    const int m = blockIdx.x * 256 + threadIdx.x;
    if (m < MTOT * KCAT) {
        const int o = m / KCAT, cs = m % KCAT;
        const int b = cs >> 6, c = cs & 63;
        const float* fcr = &fc_w[o * 384 + b * 128];
        float s = 0.f;
#pragma unroll 4
        for (int j = 0; j < 128; j++) s = fmaf(fcr[j], fuse_w[j * 64 + c], s);
        d_Wcat[m] = __float2half_rn(s);
    } else {
        const int o = m - MTOT * KCAT;
        if (o < MTOT) {
            float s = fc_b[o];
            for (int j = 0; j < 384; j++)
                s = fmaf(fc_w[o * 384 + j], fuse_b[j & 127], s);
            d_cbias[o] = s;
        }
    }
}

// ---------------- K3: f = relu(conv_w @ x + b), tf32 mma, 4-stage pipeline ----------------
__global__ void __launch_bounds__(256) k3_kernel(
    const float* __restrict__ A, const float* __restrict__ B,
    const float* __restrict__ bias, int n0) {
    constexpr int SA = 64 * 20, SB = 16 * 136, SS = SA + SB;  // floats
    constexpr int NKT = CIN / 16;
    extern __shared__ float smem[];

    const int p0 = blockIdx.y * 128;
    const int n = blockIdx.z + n0;
    const float* Bn = B + (size_t)n * CIN * HW;
    __half* Cn = d_f + (size_t)n * CMC * HW;

    const int tid = threadIdx.x;
    const int wid = tid >> 5, lane = tid & 31;
    const int wm = wid >> 2, wq = wid & 3;
    const int g = lane >> 2, tg = lane & 3;

    auto issue = [&](int s, int k0) {
        float* As_ = smem + s * SS;
        float* Bs_ = As_ + SA;
        {
            const int row = tid >> 2, kq = (tid & 3) << 2;
            cp16(&As_[row * 20 + kq], &A[(size_t)row * CIN + k0 + kq]);
        }
#pragma unroll
        for (int v = tid; v < 512; v += 256) {
            const int row = v >> 5, c4 = (v & 31) << 2;
            cp16(&Bs_[row * 136 + c4], &Bn[(size_t)(k0 + row) * HW + p0 + c4]);
        }
        cp_commit();
    };

    float acc[2][4][4];
#pragma unroll
    for (int i = 0; i < 2; i++)
#pragma unroll
        for (int j = 0; j < 4; j++)
#pragma unroll
            for (int q = 0; q < 4; q++) acc[i][j][q] = 0.f;

    issue(0, 0);
    issue(1, 16);
    issue(2, 32);

    for (int kt = 0; kt < NKT; kt++) {
        if (kt + 3 <= NKT)
            asm volatile("cp.async.wait_group 2;" ::: "memory");
        else if (kt + 2 == NKT)
            asm volatile("cp.async.wait_group 1;" ::: "memory");
        else
            asm volatile("cp.async.wait_group 0;" ::: "memory");
        __syncthreads();
        if (kt + 3 < NKT) issue((kt + 3) & 3, (kt + 3) * 16);

        const float* As_ = smem + (kt & 3) * SS;
        const float* Bs_ = As_ + SA;
#pragma unroll
        for (int ks = 0; ks < 16; ks += 8) {
            uint32_t af[2][4], bf[4][2];
#pragma unroll
            for (int i = 0; i < 2; i++) {
                const int m = wm * 32 + i * 16 + g;
                af[i][0] = __float_as_uint(f2tf32(As_[m * 20 + ks + tg]));
                af[i][1] = __float_as_uint(f2tf32(As_[(m + 8) * 20 + ks + tg]));
                af[i][2] = __float_as_uint(f2tf32(As_[m * 20 + ks + tg + 4]));
                af[i][3] = __float_as_uint(f2tf32(As_[(m + 8) * 20 + ks + tg + 4]));
            }
#pragma unroll
            for (int j = 0; j < 4; j++) {
                const int col = wq * 32 + j * 8 + g;
                bf[j][0] = __float_as_uint(f2tf32(Bs_[(ks + tg) * 136 + col]));
                bf[j][1] = __float_as_uint(f2tf32(Bs_[(ks + tg + 4) * 136 + col]));
            }
#pragma unroll
            for (int i = 0; i < 2; i++)
#pragma unroll
                for (int j = 0; j < 4; j++) mma_tf32(acc[i][j], af[i], bf[j]);
        }
    }
    // epilogue: relu + fp16 store
#pragma unroll
    for (int i = 0; i < 2; i++) {
        const int o = wm * 32 + i * 16 + g;
        const float bv0 = bias[o];
        const float bv1 = bias[o + 8];
#pragma unroll
        for (int j = 0; j < 4; j++) {
            const int px = p0 + wq * 32 + j * 8 + 2 * tg;
            *reinterpret_cast<__half2*>(&Cn[(size_t)o * HW + px]) =
                __floats2half2_rn(fmaxf(acc[i][j][0] + bv0, 0.f),
                                  fmaxf(acc[i][j][1] + bv0, 0.f));
            *reinterpret_cast<__half2*>(&Cn[(size_t)(o + 8) * HW + px]) =
                __floats2half2_rn(fmaxf(acc[i][j][2] + bv1, 0.f),
                                  fmaxf(acc[i][j][3] + bv1, 0.f));
        }
    }
}

// ---------------- K4b: out = Wcat @ ocat + cbias (fp16 HMMA + ldmatrix) ----------------
__global__ void __launch_bounds__(256) k4b_kernel(
    const __half* __restrict__ A, const float* __restrict__ bias,
    float* __restrict__ C, int n0) {
    constexpr int SA_B = 128 * 24 * 2;            // A stage bytes (half)
    constexpr int SB_B = 16 * 136 * 2;            // B stage bytes (half)
    constexpr int SS_B = SA_B + SB_B;             // 10496 B
    constexpr int NKT = KCAT / 16;
    extern __shared__ char smemc[];

    const int o0 = blockIdx.x * 128;
    const int p0 = blockIdx.y * 128;
    const int n = blockIdx.z + n0;
    const __half* Bn = d_ocat + (size_t)n * KCAT * HW;
    float* Cn = C + (size_t)n * MTOT * HW;

    const int tid = threadIdx.x;
    const int wid = tid >> 5, lane = tid & 31;
    const int wm = wid >> 2, wq = wid & 3;
    const int g = lane >> 2, tg = lane & 3;

    const int rin = lane & 7, sel = lane >> 3;
    const int a_off = (((sel & 1) << 3) + rin) * 24 + ((sel >> 1) << 3);
    const int b_off = (((sel & 1) << 3) + rin) * 136 + wq * 32 + ((sel >> 1) << 3);

    auto issue = [&](int s, int k0) {
        __half* As_ = reinterpret_cast<__half*>(smemc + s * SS_B);
        __half* Bs_ = reinterpret_cast<__half*>(smemc + s * SS_B + SA_B);
        {
            const int row = tid >> 1, kq = (tid & 1) << 3;
            cp16(&As_[row * 24 + kq], &A[(size_t)(o0 + row) * KCAT + k0 + kq]);
        }
        {
            const int row = tid >> 4, pb = (tid & 15) << 3;
            cp16(&Bs_[row * 136 + pb], &Bn[(size_t)(k0 + row) * HW + p0 + pb]);
        }
        cp_commit();
    };

    float acc[4][4][4];
#pragma unroll
    for (int i = 0; i < 4; i++)
#pragma unroll
        for (int j = 0; j < 4; j++)
#pragma unroll
            for (int q = 0; q < 4; q++) acc[i][j][q] = 0.f;

    issue(0, 0);
    issue(1, 16);
    issue(2, 32);

    for (int kt = 0; kt < NKT; kt++) {
        if (kt + 3 <= NKT)
            asm volatile("cp.async.wait_group 2;" ::: "memory");
        else if (kt + 2 == NKT)
            asm volatile("cp.async.wait_group 1;" ::: "memory");
        else
            asm volatile("cp.async.wait_group 0;" ::: "memory");
        __syncthreads();
        if (kt + 3 < NKT) issue((kt + 3) & 3, (kt + 3) * 16);

        const __half* As_ = reinterpret_cast<const __half*>(smemc + (kt & 3) * SS_B);
        const __half* Bs_ = reinterpret_cast<const __half*>(smemc + (kt & 3) * SS_B + SA_B);
        const uint32_t a_base = (uint32_t)__cvta_generic_to_shared(As_);
        const uint32_t b_base = (uint32_t)__cvta_generic_to_shared(Bs_);

        uint32_t af[4][4], bf[4][2];
#pragma unroll
        for (int i = 0; i < 4; i++) {
            const uint32_t addr = a_base + (uint32_t)(((wm * 64 + i * 16) * 24 + a_off) * 2);
            ldsm_x4(af[i][0], af[i][1], af[i][2], af[i][3], addr);
        }
#pragma unroll
        for (int jj = 0; jj < 2; jj++) {
            const uint32_t addr = b_base + (uint32_t)((b_off + jj * 16) * 2);
            ldsm_x4_t(bf[2 * jj][0], bf[2 * jj][1], bf[2 * jj + 1][0], bf[2 * jj + 1][1],
                      addr);
        }
#pragma unroll
        for (int i = 0; i < 4; i++)
#pragma unroll
            for (int j = 0; j < 4; j++) mma_f16(acc[i][j], af[i], bf[j]);
    }
    // epilogue
#pragma unroll
    for (int i = 0; i < 4; i++) {
        const int o = o0 + wm * 64 + i * 16 + g;
        const float bv0 = bias[o];
        const float bv1 = bias[o + 8];
#pragma unroll
        for (int j = 0; j < 4; j++) {
            const int px = p0 + wq * 32 + j * 8 + 2 * tg;
            *reinterpret_cast<float2*>(&Cn[(size_t)o * HW + px]) =
                make_float2(acc[i][j][0] + bv0, acc[i][j][1] + bv0);
            *reinterpret_cast<float2*>(&Cn[(size_t)(o + 8) * HW + px]) =
                make_float2(acc[i][j][2] + bv1, acc[i][j][3] + bv1);
        }
    }
}

// ---------------- K4a: depthwise convs, sliding-window 4 consecutive rows/thread ----------------
// Each thread: 4 cols x 4 consecutive rows. Union of input rows = 12 (vs 28 before).
// Per-accumulator FMA order identical to previous version -> bit-identical output.
__global__ void __launch_bounds__(256) dw_kernel(int n0) {
    const int c = blockIdx.x;  // 64
    const int n = blockIdx.y + n0;
    __shared__ float sm[72 * 72];
    __shared__ float kk[43];
    const int tid = threadIdx.x;
    for (int i = tid; i < 72 * 72; i += 256) sm[i] = 0.f;
    __syncthreads();
    const __half2* fb2 = reinterpret_cast<const __half2*>(
        d_f + ((size_t)n * CMC + c) * HW);
    for (int i = tid; i < HW / 2; i += 256) {
        const float2 v = __half22float2(fb2[i]);
        const int idx = i * 2;
        const int base = ((idx >> 6) + 4) * 72 + (idx & 63) + 4;
        sm[base] = v.x;
        sm[base + 1] = v.y;
    }
    if (tid < 43) kk[tid] = d_ker[((size_t)n * CMC + c) * 43 + tid];
    __syncthreads();

    __half* o1 = d_ocat + ((size_t)n * KCAT + c) * HW;
    __half* o2 = o1 + (size_t)64 * HW;
    __half* o3 = o1 + (size_t)128 * HW;

    const int w0 = (tid & 15) * 4;   // 16 col groups
    const int h0 = (tid >> 4) * 4;   // 16 row groups x 4 consecutive rows

    float s1[4][4], s2[4][4], s3[4][4];
#pragma unroll
    for (int r = 0; r < 4; r++)
#pragma unroll
        for (int px = 0; px < 4; px++) {
            s1[r][px] = 0.f; s2[r][px] = 0.f; s3[r][px] = 0.f;
        }

    float rv[12];
#pragma unroll
    for (int pi = 0; pi < 12; pi++) {
        // load padded row h0+pi, cols w0..w0+11
        {
            const int ri = h0 + pi;
            const float4 a = *reinterpret_cast<const float4*>(&sm[ri * 72 + w0]);
            const float4 b = *reinterpret_cast<const float4*>(&sm[ri * 72 + w0 + 4]);
            const float4 d = *reinterpret_cast<const float4*>(&sm[ri * 72 + w0 + 8]);
            rv[0] = a.x; rv[1] = a.y; rv[2] = a.z; rv[3] = a.w;
            rv[4] = b.x; rv[5] = b.y; rv[6] = b.z; rv[7] = b.w;
            rv[8] = d.x; rv[9] = d.y; rv[10] = d.z; rv[11] = d.w;
        }
#pragma unroll
        for (int rr = 0; rr < 4; rr++) {
            const int d = pi - rr;
            if (d >= 2 && d <= 6) {           // 5x5 branch, tap row dy = d-2
                const int dy = d - 2;
#pragma unroll
                for (int dx = 0; dx < 5; dx++) {
                    const float kv = kk[dy * 5 + dx];
#pragma unroll
                    for (int px = 0; px < 4; px++)
                        s1[rr][px] = fmaf(kv, rv[px + dx + 2], s1[rr][px]);
                }
            }
            if (d == 2 || d == 4 || d == 6) { // 3x3 dil-2 branch
                const int dy2 = (d - 2) >> 1;
#pragma unroll
                for (int dx = 0; dx < 3; dx++) {
                    const float kv = kk[25 + dy2 * 3 + dx];
#pragma unroll
                    for (int px = 0; px < 4; px++)
                        s2[rr][px] = fmaf(kv, rv[px + 2 * dx + 2], s2[rr][px]);
                }
            }
            if (d == 0 || d == 4 || d == 8) { // 3x3 dil-4 branch
                const int dy4 = d >> 2;
#pragma unroll
                for (int dx = 0; dx < 3; dx++) {
                    const float kv = kk[34 + dy4 * 3 + dx];
#pragma unroll
                    for (int px = 0; px < 4; px++)
                        s3[rr][px] = fmaf(kv, rv[px + 4 * dx], s3[rr][px]);
                }
            }
        }
    }

#pragma unroll
    for (int rr = 0; rr < 4; rr++) {
        const int i0 = (h0 + rr) * 64 + w0;
        union { uint2 u; __half2 h[2]; } pk;
        pk.h[0] = __floats2half2_rn(s1[rr][0], s1[rr][1]);
        pk.h[1] = __floats2half2_rn(s1[rr][2], s1[rr][3]);
        *reinterpret_cast<uint2*>(&o1[i0]) = pk.u;
        pk.h[0] = __floats2half2_rn(s2[rr][0], s2[rr][1]);
        pk.h[1] = __floats2half2_rn(s2[rr][2], s2[rr][3]);
        *reinterpret_cast<uint2*>(&o2[i0]) = pk.u;
        pk.h[0] = __floats2half2_rn(s3[rr][0], s3[rr][1]);
        pk.h[1] = __floats2half2_rn(s3[rr][2], s3[rr][3]);
        *reinterpret_cast<uint2*>(&o3[i0]) = pk.u;
    }
}

// ---------------- host launch: two batch-half pipelines on forked streams ----------------
extern "C" void kernel_launch(void* const* d_in, const int* in_sizes, int n_in,
                              void* d_out, int out_size) {
    (void)in_sizes; (void)n_in; (void)out_size;
    const float* x      = (const float*)d_in[0];
    const float* conv_w = (const float*)d_in[1];
    const float* conv_b = (const float*)d_in[2];
    const float* ckw    = (const float*)d_in[3];
    const float* ckb    = (const float*)d_in[4];
    const float* ck2w   = (const float*)d_in[5];
    const float* ck2b   = (const float*)d_in[6];
    const float* ckd4w  = (const float*)d_in[7];
    const float* ckd4b  = (const float*)d_in[8];
    const float* kw     = (const float*)d_in[9];
    const float* kb     = (const float*)d_in[10];
    const float* k2w    = (const float*)d_in[11];
    const float* k2b    = (const float*)d_in[12];
    const float* kd4w   = (const float*)d_in[13];
    const float* kd4b   = (const float*)d_in[14];
    const float* fuse_w = (const float*)d_in[15];
    const float* fuse_b = (const float*)d_in[16];
    const float* fc_w   = (const float*)d_in[17];
    const float* fc_b   = (const float*)d_in[18];
    float* out = (float*)d_out;

    void *p_Wcat = nullptr, *p_cbias = nullptr;
    cudaGetSymbolAddress(&p_Wcat, d_Wcat);
    cudaGetSymbolAddress(&p_cbias, d_cbias);

    constexpr int SMEM_K3  = 4 * (64 * 20 + 16 * 136) * 4;                // 55296 B
    constexpr int SMEM_K4B = 4 * (128 * 24 * 2 + 16 * 136 * 2);           // 41984 B

    // one-time resources (created on the uncaptured correctness call; reused under capture)
    static cudaStream_t sA = nullptr, sB = nullptr;
    static cudaEvent_t evRoot = nullptr, evW = nullptr, evA = nullptr, evB = nullptr;
    if (sA == nullptr) {
        cudaStreamCreateWithFlags(&sA, cudaStreamNonBlocking);
        cudaStreamCreateWithFlags(&sB, cudaStreamNonBlocking);
        cudaEventCreateWithFlags(&evRoot, cudaEventDisableTiming);
        cudaEventCreateWithFlags(&evW, cudaEventDisableTiming);
        cudaEventCreateWithFlags(&evA, cudaEventDisableTiming);
        cudaEventCreateWithFlags(&evB, cudaEventDisableTiming);
        cudaFuncSetAttribute(k3_kernel, cudaFuncAttributeMaxDynamicSharedMemorySize,
                             SMEM_K3);
        cudaFuncSetAttribute(k4b_kernel, cudaFuncAttributeMaxDynamicSharedMemorySize,
                             SMEM_K4B);
    }

    // fork from the (captured) default stream
    cudaEventRecord(evRoot, 0);
    cudaStreamWaitEvent(sA, evRoot, 0);
    cudaStreamWaitEvent(sB, evRoot, 0);

    // ---- stream A: shared wcat + batch half [0,16) ----
    wcat_kernel<<<(MTOT * KCAT + MTOT + 255) / 256, 256, 0, sA>>>(fc_w, fc_b, fuse_w,
                                                                  fuse_b);
    cudaEventRecord(evW, sA);
    mean_kernel<<<NBH * CIN, 256, 0, sA>>>(x, 0);
    gker_kernel<<<128, 256, 0, sA>>>(conv_w, conv_b, ckw, ckb, ck2w, ck2b, ckd4w, ckd4b,
                                     kw, kb, k2w, k2b, kd4w, kd4b, 0);
    k3_kernel<<<dim3(1, HW / 128, NBH), 256, SMEM_K3, sA>>>(conv_w, x, conv_b, 0);
    dw_kernel<<<dim3(CMC, NBH), 256, 0, sA>>>(0);
    k4b_kernel<<<dim3(MTOT / 128, HW / 128, NBH), 256, SMEM_K4B, sA>>>(
        (const __half*)p_Wcat, (const float*)p_cbias, out, 0);

    // ---- stream B: batch half [16,32) ----
    mean_kernel<<<NBH * CIN, 256, 0, sB>>>(x, NBH);
    gker_kernel<<<128, 256, 0, sB>>>(conv_w, conv_b, ckw, ckb, ck2w, ck2b, ckd4w, ckd4b,
                                     kw, kb, k2w, k2b, kd4w, kd4b, NBH);
    k3_kernel<<<dim3(1, HW / 128, NBH), 256, SMEM_K3, sB>>>(conv_w, x, conv_b, NBH);
    dw_kernel<<<dim3(CMC, NBH), 256, 0, sB>>>(NBH);
    cudaStreamWaitEvent(sB, evW, 0);  // k4b needs Wcat/cbias
    k4b_kernel<<<dim3(MTOT / 128, HW / 128, NBH), 256, SMEM_K4B, sB>>>(
        (const __half*)p_Wcat, (const float*)p_cbias, out, NBH);

    // join back to the default stream
    cudaEventRecord(evA, sA);
    cudaEventRecord(evB, sB);
    cudaStreamWaitEvent(0, evA, 0);
    cudaStreamWaitEvent(0, evB, 0);
}